// round 13
// baseline (speedup 1.0000x reference)
#include <cuda_runtime.h>
#include <cuda_bf16.h>
#include <math.h>
#include <stdint.h>

// ---------------- problem constants ----------------
#define LTOK 8192
#define HDIM 1280
#define NHEAD 16
#define HEADD 80
#define MHID 3420
#define MH_P 3424
#define GU_N 6848          // interleaved gate|up width (2 * MH_P)
#define NBLK 4
#define NWIN 128
#define PDIM 1176
#define DMODEL 3584
#define H4 5120
#define LMERG 2048

// ---------------- fp32 scratch ----------------
static constexpr long SZ_LH  = (long)LTOK * HDIM;
static constexpr long SZ_L3H = (long)LTOK * 3 * HDIM;

static constexpr long F_X    = 0;
static constexpr long F_RES  = F_X   + SZ_LH;
static constexpr long F_HB   = F_RES + SZ_LH;
static constexpr long F_QKV  = F_HB  + SZ_LH;
static constexpr long F_M0   = F_QKV + SZ_L3H;           // merger m0 out [LMERG][H4]
static constexpr long F_TOTAL = F_M0 + (long)LMERG * H4;
__device__ float g_f32[F_TOTAL];

__device__ float g_bias[NBLK * GU_N];

// ---------------- bf16 scratch (hi/lo pairs) ----------------
static constexpr long SZ_XS  = (long)LTOK * PDIM;
static constexpr long SZ_PW  = (long)PDIM * HDIM;
static constexpr long SZ_QW  = (long)NBLK * HDIM * 3*HDIM;
static constexpr long SZ_PRW = (long)NBLK * HDIM * HDIM;
static constexpr long SZ_GU  = (long)NBLK * HDIM * GU_N;
static constexpr long SZ_DW  = (long)NBLK * MHID * HDIM;
static constexpr long SZ_M0W = (long)H4 * H4;
static constexpr long SZ_M2W = (long)H4 * DMODEL;
static constexpr long SZ_SHP = (long)LTOK * MH_P;

static constexpr long B_XH  = 0;
static constexpr long B_XL  = B_XH + SZ_XS;
static constexpr long B_NH  = B_XL + SZ_XS;
static constexpr long B_NL  = B_NH + SZ_LH;
static constexpr long B_AH  = B_NL + SZ_LH;
static constexpr long B_AL  = B_AH + SZ_LH;
static constexpr long B_SH  = B_AL + SZ_LH;
static constexpr long B_SL  = B_SH + SZ_SHP;
static constexpr long B_PW  = B_SL + SZ_SHP;
static constexpr long B_QW  = B_PW + 2*SZ_PW;
static constexpr long B_PRW = B_QW + 2*SZ_QW;
static constexpr long B_GUH = B_PRW + 2*SZ_PRW;
static constexpr long B_GUL = B_GUH + SZ_GU;
static constexpr long B_DW  = B_GUL + SZ_GU;
static constexpr long B_M0W = B_DW + 2*SZ_DW;
static constexpr long B_M2W = B_M0W + 2*SZ_M0W;
static constexpr long B_TOTAL = B_M2W + 2*SZ_M2W;
__device__ __nv_bfloat16 g_bf16[B_TOTAL];

// ---------------- PTX helpers (base sm_103 target only!) ----------------
__device__ __forceinline__ uint32_t smem_to_u32(const void* p) {
    uint32_t a;
    asm("{ .reg .u64 t; cvta.to.shared.u64 t, %1; cvt.u32.u64 %0, t; }" : "=r"(a) : "l"(p));
    return a;
}
__device__ __forceinline__ void cp16(uint32_t dst, const void* src, int bytes) {
    asm volatile("cp.async.cg.shared.global [%0], [%1], 16, %2;"
                 :: "r"(dst), "l"(src), "r"(bytes));
}
#define CP_COMMIT() asm volatile("cp.async.commit_group;" ::: "memory")
#define CP_WAIT2()  asm volatile("cp.async.wait_group 2;" ::: "memory")

__device__ __forceinline__ void ldsm_x4(uint32_t r[4], uint32_t addr) {
    asm volatile("ldmatrix.sync.aligned.m8n8.x4.shared.b16 {%0,%1,%2,%3}, [%4];"
                 : "=r"(r[0]), "=r"(r[1]), "=r"(r[2]), "=r"(r[3]) : "r"(addr));
}
__device__ __forceinline__ void ldsm_x4t(uint32_t r[4], uint32_t addr) {
    asm volatile("ldmatrix.sync.aligned.m8n8.x4.trans.shared.b16 {%0,%1,%2,%3}, [%4];"
                 : "=r"(r[0]), "=r"(r[1]), "=r"(r[2]), "=r"(r[3]) : "r"(addr));
}
__device__ __forceinline__ void mma_bf16(float c[4], const uint32_t a[4],
                                         uint32_t b0, uint32_t b1) {
    asm volatile(
        "mma.sync.aligned.m16n8k16.row.col.f32.bf16.bf16.f32 "
        "{%0,%1,%2,%3}, {%4,%5,%6,%7}, {%8,%9}, {%0,%1,%2,%3};"
        : "+f"(c[0]), "+f"(c[1]), "+f"(c[2]), "+f"(c[3])
        : "r"(a[0]), "r"(a[1]), "r"(a[2]), "r"(a[3]), "r"(b0), "r"(b1));
}

// ---------------- tensor-core GEMM (bf16x3 split, fp32 accum, optional split-K) ----------------
enum { E_NONE = 0, E_BIAS = 1, E_BIAS_RES = 2, E_SWIGLU = 3 };

#define A_STRIDE 40
#define B_STRIDE 136
#define A_TILE_B (128 * A_STRIDE * 2)      // 10240
#define B_TILE_B (32 * B_STRIDE * 2)       // 8704
#define STAGE_B  (2 * A_TILE_B + 2 * B_TILE_B)  // 37888
#define OFF_AH 0
#define OFF_AL A_TILE_B
#define OFF_BH (2 * A_TILE_B)
#define OFF_BL (2 * A_TILE_B + B_TILE_B)
#define GEMM_SMEM (3 * STAGE_B)            // 113664
#define GT 256

template<int EPI>
__global__ void __launch_bounds__(GT, 2) tcgemm_kernel(
    const __nv_bfloat16* __restrict__ Ah, const __nv_bfloat16* __restrict__ Al,
    const __nv_bfloat16* __restrict__ Bh, const __nv_bfloat16* __restrict__ Bl,
    const float* __restrict__ bias, const float* __restrict__ res,
    float* __restrict__ C, __nv_bfloat16* __restrict__ Oh, __nv_bfloat16* __restrict__ Ol,
    int M, int N, int K, int lda, int ldb, int ldc)
{
    extern __shared__ __align__(16) char sm[];
    const uint32_t smem_u = smem_to_u32(sm);
    const int tid = threadIdx.x;
    const int lane = tid & 31, wid = tid >> 5;
    const int wm = wid >> 2, wn = wid & 3;
    const int row0 = blockIdx.y * 128, col0 = blockIdx.x * 128;

    const int nc_tot = (K + 31) / 32;
    const int S = gridDim.z;
    const int per = (nc_tot + S - 1) / S;
    const int c0 = blockIdx.z * per;
    int c1 = c0 + per; if (c1 > nc_tot) c1 = nc_tot;
    const int myn = (c1 > c0) ? (c1 - c0) : 0;

    auto load_stage = [&](int st, int c) {
        const uint32_t sbase = smem_u + st * STAGE_B;
        const int k0 = c * 32;
        #pragma unroll
        for (int h = 0; h < 2; ++h) {
            const __nv_bfloat16* src = h ? Al : Ah;
            const uint32_t dbase = sbase + (h ? OFF_AL : OFF_AH);
            #pragma unroll
            for (int it = 0; it < 2; ++it) {
                int e = tid + it * 256;
                int r = e >> 2, q = e & 3;
                int gr = row0 + r;
                int gk = k0 + q * 8;
                int bytes = (K - gk) * 2;
                bytes = bytes < 0 ? 0 : (bytes > 16 ? 16 : bytes);
                const __nv_bfloat16* g = src + (long)gr * lda + (bytes > 0 ? gk : 0);
                cp16(dbase + r * (A_STRIDE * 2) + q * 16, g, bytes);
            }
        }
        #pragma unroll
        for (int h = 0; h < 2; ++h) {
            const __nv_bfloat16* src = h ? Bl : Bh;
            const uint32_t dbase = sbase + (h ? OFF_BL : OFF_BH);
            #pragma unroll
            for (int it = 0; it < 2; ++it) {
                int e = tid + it * 256;
                int r = e >> 4, q = e & 15;
                int gk = k0 + r;
                int gc = col0 + q * 8;
                int bytes = (N - gc) * 2;
                bytes = bytes < 0 ? 0 : (bytes > 16 ? 16 : bytes);
                if (gk >= K) bytes = 0;
                const __nv_bfloat16* g = src + (long)(gk < K ? gk : 0) * ldb + (bytes > 0 ? gc : 0);
                cp16(dbase + r * (B_STRIDE * 2) + q * 16, g, bytes);
            }
        }
    };

    const int a_row = lane & 15;
    const int a_kh = (lane >> 4) * 8;
    const int b_g = lane >> 3, b_l = lane & 7;
    const int b_k = (b_g & 1) * 8 + b_l;
    const int b_n = (b_g >> 1) * 8;

    float acc[4][4][4];
    #pragma unroll
    for (int i = 0; i < 4; ++i)
        #pragma unroll
        for (int j = 0; j < 4; ++j)
            #pragma unroll
            for (int r = 0; r < 4; ++r) acc[i][j][r] = 0.f;

    #pragma unroll
    for (int s = 0; s < 3; ++s) {
        if (s < myn) load_stage(s, c0 + s);
        CP_COMMIT();
    }

    for (int cc = 0; cc < myn; ++cc) {
        CP_WAIT2();
        __syncthreads();
        const int st = cc % 3;
        const uint32_t sbase = smem_u + st * STAGE_B;
        const uint32_t aB[2] = { sbase + OFF_AH, sbase + OFF_AL };
        const uint32_t bB[2] = { sbase + OFF_BH, sbase + OFF_BL };

        #pragma unroll
        for (int ks = 0; ks < 2; ++ks) {
            uint32_t af[2][4][4];
            #pragma unroll
            for (int h = 0; h < 2; ++h)
                #pragma unroll
                for (int i = 0; i < 4; ++i)
                    ldsm_x4(af[h][i],
                        aB[h] + 2u * ((wm * 64 + i * 16 + a_row) * A_STRIDE + ks * 16 + a_kh));
            #pragma unroll
            for (int j2 = 0; j2 < 2; ++j2) {
                uint32_t b0[4], b1[4];
                uint32_t boff = 2u * ((ks * 16 + b_k) * B_STRIDE + wn * 32 + j2 * 16 + b_n);
                ldsm_x4t(b0, bB[0] + boff);
                ldsm_x4t(b1, bB[1] + boff);
                #pragma unroll
                for (int i = 0; i < 4; ++i) {
                    mma_bf16(acc[i][2*j2],   af[0][i], b0[0], b0[1]);
                    mma_bf16(acc[i][2*j2+1], af[0][i], b0[2], b0[3]);
                    mma_bf16(acc[i][2*j2],   af[0][i], b1[0], b1[1]);
                    mma_bf16(acc[i][2*j2+1], af[0][i], b1[2], b1[3]);
                    mma_bf16(acc[i][2*j2],   af[1][i], b0[0], b0[1]);
                    mma_bf16(acc[i][2*j2+1], af[1][i], b0[2], b0[3]);
                }
            }
        }
        __syncthreads();
        if (cc + 3 < myn) load_stage(st, c0 + cc + 3);
        CP_COMMIT();
    }

    const bool add_const = (blockIdx.z == 0);
    const int g = lane >> 2, t = lane & 3;
    #pragma unroll
    for (int i = 0; i < 4; ++i) {
        #pragma unroll
        for (int j = 0; j < 4; ++j) {
            int col = col0 + wn * 32 + j * 8 + t * 2;
            if (col >= N) continue;
            float b0 = 0.f, b1 = 0.f;
            if (EPI != E_NONE && add_const) { b0 = bias[col]; b1 = bias[col + 1]; }
            #pragma unroll
            for (int rr = 0; rr < 2; ++rr) {
                int row = row0 + wm * 64 + i * 16 + g + rr * 8;
                if (row >= M) continue;
                float v0 = acc[i][j][rr * 2 + 0] + b0;
                float v1 = acc[i][j][rr * 2 + 1] + b1;
                if (EPI == E_SWIGLU) {
                    // interleaved layout: v0 = gate_j, v1 = up_j, j = col/2
                    float sw = v0 / (1.f + __expf(-v0)) * v1;
                    __nv_bfloat16 hh = __float2bfloat16(sw);
                    long oidx = (long)row * MH_P + (col >> 1);
                    Oh[oidx] = hh;
                    Ol[oidx] = __float2bfloat16(sw - __bfloat162float(hh));
                    continue;
                }
                long idx = (long)row * ldc + col;
                if (EPI == E_BIAS_RES && add_const) { v0 += res[idx]; v1 += res[idx + 1]; }
                if (gridDim.z == 1) {
                    *reinterpret_cast<float2*>(C + idx) = make_float2(v0, v1);
                } else {
                    atomicAdd(C + idx, v0);
                    atomicAdd(C + idx + 1, v1);
                }
            }
        }
    }
}

// ---------------- fused windowed attention with inline RoPE (fp32) ----------------
#define SP 81
#define ATTN_SMEM (3 * 64 * SP * 4)

__global__ void __launch_bounds__(256) attn_kernel(
    const float* __restrict__ qkv, const float* __restrict__ cosb,
    const float* __restrict__ sinb, __nv_bfloat16* __restrict__ outH,
    __nv_bfloat16* __restrict__ outL)
{
    extern __shared__ float smf[];
    float* q = smf;
    float* k = smf + 64 * SP;
    float* v = smf + 2 * 64 * SP;
    float* s = smf;                 // aliases q (dead after QK phase)

    const int w = blockIdx.x >> 4;
    const int h = blockIdx.x & 15;
    const int tid = threadIdx.x;
    const float scale = 0.11180339887498949f;

    for (int e = tid; e < 64 * 80; e += 256) {
        int t = e / 80, j = e % 80;
        int l = w * 64 + t;
        long base = (long)l * (3 * HDIM) + h * 80;
        float c = cosb[l * 80 + j], sn = sinb[l * 80 + j];
        float qv = qkv[base + j];
        float qr = (j < 40) ? -qkv[base + j + 40] : qkv[base + j - 40];
        q[t * SP + j] = qv * c + qr * sn;
        float kv = qkv[base + HDIM + j];
        float kr = (j < 40) ? -qkv[base + HDIM + j + 40] : qkv[base + HDIM + j - 40];
        k[t * SP + j] = kv * c + kr * sn;
        v[t * SP + j] = qkv[base + 2 * HDIM + j];
    }
    __syncthreads();

    {
        const int tx = tid & 15, ty = tid >> 4;
        float acc[4][4] = {};
        for (int d = 0; d < 80; d++) {
            float qa[4], kb[4];
            #pragma unroll
            for (int i = 0; i < 4; i++) qa[i] = q[(ty * 4 + i) * SP + d];
            #pragma unroll
            for (int j = 0; j < 4; j++) kb[j] = k[(tx * 4 + j) * SP + d];
            #pragma unroll
            for (int i = 0; i < 4; i++)
                #pragma unroll
                for (int j = 0; j < 4; j++)
                    acc[i][j] += qa[i] * kb[j];
        }
        __syncthreads();
        #pragma unroll
        for (int i = 0; i < 4; i++)
            #pragma unroll
            for (int j = 0; j < 4; j++)
                s[(ty * 4 + i) * 64 + tx * 4 + j] = acc[i][j] * scale;
    }
    __syncthreads();

    {
        const int warp = tid >> 5, lane = tid & 31;
        for (int r = warp; r < 64; r += 8) {
            float x0 = s[r * 64 + lane], x1 = s[r * 64 + 32 + lane];
            float mx = fmaxf(x0, x1);
            #pragma unroll
            for (int o = 16; o > 0; o >>= 1) mx = fmaxf(mx, __shfl_xor_sync(~0u, mx, o));
            float e0 = __expf(x0 - mx), e1 = __expf(x1 - mx);
            float sum = e0 + e1;
            #pragma unroll
            for (int o = 16; o > 0; o >>= 1) sum += __shfl_xor_sync(~0u, sum, o);
            float inv = 1.f / sum;
            s[r * 64 + lane] = e0 * inv;
            s[r * 64 + 32 + lane] = e1 * inv;
        }
    }
    __syncthreads();

    {
        const int tx = tid & 15, ty = tid >> 4;
        float acc[4][5] = {};
        for (int kk = 0; kk < 64; kk++) {
            float sa[4], vb[5];
            #pragma unroll
            for (int i = 0; i < 4; i++) sa[i] = s[(ty * 4 + i) * 64 + kk];
            #pragma unroll
            for (int j = 0; j < 5; j++) vb[j] = v[kk * SP + tx * 5 + j];
            #pragma unroll
            for (int i = 0; i < 4; i++)
                #pragma unroll
                for (int j = 0; j < 5; j++)
                    acc[i][j] += sa[i] * vb[j];
        }
        #pragma unroll
        for (int i = 0; i < 4; i++) {
            long obase = (long)(w * 64 + ty * 4 + i) * HDIM + h * 80 + tx * 5;
            #pragma unroll
            for (int j = 0; j < 5; j++) {
                float val = acc[i][j];
                __nv_bfloat16 hh = __float2bfloat16(val);
                outH[obase + j] = hh;
                outL[obase + j] = __float2bfloat16(val - __bfloat162float(hh));
            }
        }
    }
}

// ---------------- fused (optional add) + RMSNorm, bf16 hi/lo out ----------------
__global__ void __launch_bounds__(256) rmsnorm_kernel(
    const float* __restrict__ a, const float* __restrict__ b,
    const float* __restrict__ w, float* __restrict__ sum_out,
    __nv_bfloat16* __restrict__ nh, __nv_bfloat16* __restrict__ nl)
{
    __shared__ float sv[HDIM];
    __shared__ float red[8];
    __shared__ float s_scale;
    const int row = blockIdx.x, tid = threadIdx.x;
    const long base = (long)row * HDIM;
    float ss = 0.f;
    for (int j = tid; j < HDIM; j += 256) {
        float v = a[base + j];
        if (b) v += b[base + j];
        sv[j] = v;
        if (sum_out) sum_out[base + j] = v;
        ss += v * v;
    }
    #pragma unroll
    for (int o = 16; o > 0; o >>= 1) ss += __shfl_xor_sync(~0u, ss, o);
    if ((tid & 31) == 0) red[tid >> 5] = ss;
    __syncthreads();
    if (tid == 0) {
        float t = 0.f;
        #pragma unroll
        for (int i = 0; i < 8; i++) t += red[i];
        s_scale = rsqrtf(t / (float)HDIM + 1e-6f);
    }
    __syncthreads();
    float sc = s_scale;
    for (int j = tid; j < HDIM; j += 256) {
        float v = sv[j] * sc * w[j];
        __nv_bfloat16 hh = __float2bfloat16(v);
        nh[base + j] = hh;
        nl[base + j] = __float2bfloat16(v - __bfloat162float(hh));
    }
}

// ---------------- standalone GELU + bf16 hi/lo split (for split-K m0) ----------------
__global__ void __launch_bounds__(256) gelu_split_kernel(
    const float* __restrict__ in, __nv_bfloat16* __restrict__ oh,
    __nv_bfloat16* __restrict__ ol, long n4)
{
    for (long i = (long)blockIdx.x * 256 + threadIdx.x; i < n4; i += (long)gridDim.x * 256) {
        float4 v = *reinterpret_cast<const float4*>(in + 4 * i);
        float vv[4] = {v.x, v.y, v.z, v.w};
        __nv_bfloat16 th[4], tl[4];
        #pragma unroll
        for (int j = 0; j < 4; j++) {
            float x = vv[j];
            float g = 0.5f * x * (1.f + erff(x * 0.70710678118654752f));
            __nv_bfloat16 hh = __float2bfloat16(g);
            th[j] = hh;
            tl[j] = __float2bfloat16(g - __bfloat162float(hh));
        }
        *reinterpret_cast<uint2*>(oh + 4 * i) = *reinterpret_cast<uint2*>(th);
        *reinterpret_cast<uint2*>(ol + 4 * i) = *reinterpret_cast<uint2*>(tl);
    }
}

// ---------------- interleaved gate|up weight split: out[r][2j]=gate, out[r][2j+1]=up ----------------
__global__ void __launch_bounds__(256) split_interleave_kernel(
    const float* __restrict__ gw, const float* __restrict__ uw,
    __nv_bfloat16* __restrict__ h, __nv_bfloat16* __restrict__ l, int rows)
{
    const int j4n = MH_P / 4;     // 856
    long total = (long)rows * j4n;
    for (long i = (long)blockIdx.x * 256 + threadIdx.x; i < total; i += (long)gridDim.x * 256) {
        int r = (int)(i / j4n);
        int j0 = (int)(i - (long)r * j4n) * 4;
        __nv_bfloat16 th[8], tl[8];
        #pragma unroll
        for (int jj = 0; jj < 4; ++jj) {
            int j = j0 + jj;
            float gv = (j < MHID) ? gw[(long)r * MHID + j] : 0.f;
            float uv = (j < MHID) ? uw[(long)r * MHID + j] : 0.f;
            __nv_bfloat16 gh = __float2bfloat16(gv);
            __nv_bfloat16 uh = __float2bfloat16(uv);
            th[2*jj]   = gh;
            th[2*jj+1] = uh;
            tl[2*jj]   = __float2bfloat16(gv - __bfloat162float(gh));
            tl[2*jj+1] = __float2bfloat16(uv - __bfloat162float(uh));
        }
        long o = (long)r * GU_N + 2 * j0;
        *reinterpret_cast<uint4*>(h + o) = *reinterpret_cast<uint4*>(th);
        *reinterpret_cast<uint4*>(l + o) = *reinterpret_cast<uint4*>(tl);
    }
}

// ---------------- interleaved gate|up bias fill ----------------
__global__ void __launch_bounds__(256) fill_bias_kernel(
    const float* __restrict__ gate_b, const float* __restrict__ up_b, float* __restrict__ out)
{
    int i = blockIdx.x * 256 + threadIdx.x;
    if (i >= NBLK * GU_N) return;
    int d = i / GU_N, c = i - d * GU_N;
    int j = c >> 1;
    float v = 0.f;
    if (j < MHID) v = (c & 1) ? up_b[d * MHID + j] : gate_b[d * MHID + j];
    out[i] = v;
}

// ---------------- fp32 -> bf16 hi/lo splits ----------------
__global__ void __launch_bounds__(256) split_kernel(
    const float4* __restrict__ in, __nv_bfloat16* __restrict__ h,
    __nv_bfloat16* __restrict__ l, long n4)
{
    for (long i = (long)blockIdx.x * 256 + threadIdx.x; i < n4; i += (long)gridDim.x * 256) {
        float4 v = in[i];
        __nv_bfloat16 th[4], tl[4];
        float vv[4] = {v.x, v.y, v.z, v.w};
        #pragma unroll
        for (int j = 0; j < 4; j++) {
            th[j] = __float2bfloat16(vv[j]);
            tl[j] = __float2bfloat16(vv[j] - __bfloat162float(th[j]));
        }
        *reinterpret_cast<uint2*>(h + 4 * i) = *reinterpret_cast<uint2*>(th);
        *reinterpret_cast<uint2*>(l + 4 * i) = *reinterpret_cast<uint2*>(tl);
    }
}

// ---------------- host ----------------
static inline dim3 ggrid(int M, int N, int S = 1) {
    return dim3((N + 127) / 128, (M + 127) / 128, S);
}

static inline void do_split(const float* src, __nv_bfloat16* h, __nv_bfloat16* l, long n) {
    long n4 = n / 4;
    int blocks = (int)((n4 + 255) / 256);
    if (blocks > 16384) blocks = 16384;
    split_kernel<<<blocks, 256>>>((const float4*)src, h, l, n4);
}

extern "C" void kernel_launch(void* const* d_in, const int* in_sizes, int n_in,
                              void* d_out, int out_size)
{
    const float* x       = (const float*)d_in[0];
    const float* cosb    = (const float*)d_in[1];
    const float* sinb    = (const float*)d_in[2];
    const float* patch_w = (const float*)d_in[3];
    const float* norm1_w = (const float*)d_in[4];
    const float* norm2_w = (const float*)d_in[5];
    const float* qkv_w   = (const float*)d_in[6];
    const float* qkv_b   = (const float*)d_in[7];
    const float* proj_w  = (const float*)d_in[8];
    const float* proj_b  = (const float*)d_in[9];
    const float* gate_w  = (const float*)d_in[10];
    const float* gate_b  = (const float*)d_in[11];
    const float* up_w    = (const float*)d_in[12];
    const float* up_b    = (const float*)d_in[13];
    const float* down_w  = (const float*)d_in[14];
    const float* down_b  = (const float*)d_in[15];
    const float* lnq_w   = (const float*)d_in[16];
    const float* m0_w    = (const float*)d_in[17];
    const float* m0_b    = (const float*)d_in[18];
    const float* m2_w    = (const float*)d_in[19];
    const float* m2_b    = (const float*)d_in[20];

    float* fs = nullptr;
    __nv_bfloat16* bs = nullptr;
    float* gub = nullptr;
    cudaGetSymbolAddress((void**)&fs, g_f32);
    cudaGetSymbolAddress((void**)&bs, g_bf16);
    cudaGetSymbolAddress((void**)&gub, g_bias);

    float* pX    = fs + F_X;
    float* pRES  = fs + F_RES;
    float* pHB   = fs + F_HB;
    float* pQKV  = fs + F_QKV;
    float* pM0   = fs + F_M0;

    __nv_bfloat16 *xH = bs+B_XH, *xL = bs+B_XL;
    __nv_bfloat16 *nH = bs+B_NH, *nL = bs+B_NL;
    __nv_bfloat16 *aH = bs+B_AH, *aL = bs+B_AL;
    __nv_bfloat16 *sH = bs+B_SH, *sL = bs+B_SL;
    __nv_bfloat16 *pwH = bs+B_PW,  *pwL = pwH + SZ_PW;
    __nv_bfloat16 *qwH = bs+B_QW,  *qwL = qwH + SZ_QW;
    __nv_bfloat16 *prH = bs+B_PRW, *prL = prH + SZ_PRW;
    __nv_bfloat16 *guH = bs+B_GUH, *guL = bs+B_GUL;
    __nv_bfloat16 *dwH = bs+B_DW,  *dwL = dwH + SZ_DW;
    __nv_bfloat16 *m0H = bs+B_M0W, *m0L = m0H + SZ_M0W;
    __nv_bfloat16 *m2H = bs+B_M2W, *m2L = m2H + SZ_M2W;

    cudaFuncSetAttribute(tcgemm_kernel<E_NONE>, cudaFuncAttributeMaxDynamicSharedMemorySize, GEMM_SMEM);
    cudaFuncSetAttribute(tcgemm_kernel<E_BIAS>, cudaFuncAttributeMaxDynamicSharedMemorySize, GEMM_SMEM);
    cudaFuncSetAttribute(tcgemm_kernel<E_BIAS_RES>, cudaFuncAttributeMaxDynamicSharedMemorySize, GEMM_SMEM);
    cudaFuncSetAttribute(tcgemm_kernel<E_SWIGLU>, cudaFuncAttributeMaxDynamicSharedMemorySize, GEMM_SMEM);
    cudaFuncSetAttribute(attn_kernel, cudaFuncAttributeMaxDynamicSharedMemorySize, ATTN_SMEM);

    do_split(x,       xH,  xL,  SZ_XS);
    do_split(patch_w, pwH, pwL, SZ_PW);
    do_split(qkv_w,   qwH, qwL, SZ_QW);
    do_split(proj_w,  prH, prL, SZ_PRW);
    split_interleave_kernel<<<16384, 256>>>(gate_w, up_w, guH, guL, NBLK * HDIM);

    // patch embed (split-K S=4, atomic)
    cudaMemsetAsync(pX, 0, SZ_LH * sizeof(float));
    tcgemm_kernel<E_NONE><<<ggrid(LTOK, HDIM, 4), GT, GEMM_SMEM>>>(
        xH, xL, pwH, pwL, nullptr, nullptr, pX, nullptr, nullptr,
        LTOK, HDIM, PDIM, PDIM, HDIM, HDIM);

    do_split(down_w,  dwH, dwL, SZ_DW);
    do_split(m0_w,    m0H, m0L, SZ_M0W);
    do_split(m2_w,    m2H, m2L, SZ_M2W);
    fill_bias_kernel<<<(NBLK * GU_N + 255) / 256, 256>>>(gate_b, up_b, gub);

    for (int d = 0; d < NBLK; d++) {
        rmsnorm_kernel<<<LTOK, 256>>>(pX, d == 0 ? nullptr : pRES,
                                      norm1_w + (long)d * HDIM, pHB, nH, nL);
        // qkv (split-K S=2, atomic)
        cudaMemsetAsync(pQKV, 0, SZ_L3H * sizeof(float));
        tcgemm_kernel<E_BIAS><<<ggrid(LTOK, 3 * HDIM, 2), GT, GEMM_SMEM>>>(
            nH, nL, qwH + (long)d * HDIM * 3 * HDIM, qwL + (long)d * HDIM * 3 * HDIM,
            qkv_b + (long)d * 3 * HDIM, nullptr, pQKV, nullptr, nullptr,
            LTOK, 3 * HDIM, HDIM, HDIM, 3 * HDIM, 3 * HDIM);
        attn_kernel<<<NWIN * NHEAD, 256, ATTN_SMEM>>>(pQKV, cosb, sinb, aH, aL);
        // proj + residual (split-K S=4, atomic; bias+res added by z=0)
        cudaMemsetAsync(pRES, 0, SZ_LH * sizeof(float));
        tcgemm_kernel<E_BIAS_RES><<<ggrid(LTOK, HDIM, 4), GT, GEMM_SMEM>>>(
            aH, aL, prH + (long)d * HDIM * HDIM, prL + (long)d * HDIM * HDIM,
            proj_b + (long)d * HDIM, pHB, pRES, nullptr, nullptr,
            LTOK, HDIM, HDIM, HDIM, HDIM, HDIM);
        rmsnorm_kernel<<<LTOK, 256>>>(pRES, nullptr, norm2_w + (long)d * HDIM, nullptr, nH, nL);
        // merged interleaved gate|up GEMM with fused swiglu epilogue -> sH/sL
        tcgemm_kernel<E_SWIGLU><<<ggrid(LTOK, GU_N), GT, GEMM_SMEM>>>(
            nH, nL, guH + (long)d * HDIM * GU_N, guL + (long)d * HDIM * GU_N,
            gub + (long)d * GU_N, nullptr, nullptr, sH, sL,
            LTOK, GU_N, HDIM, HDIM, GU_N, GU_N);
        // down (split-K S=4, atomic)
        cudaMemsetAsync(pX, 0, SZ_LH * sizeof(float));
        tcgemm_kernel<E_BIAS><<<ggrid(LTOK, HDIM, 4), GT, GEMM_SMEM>>>(
            sH, sL, dwH + (long)d * MHID * HDIM, dwL + (long)d * MHID * HDIM,
            down_b + (long)d * HDIM, nullptr, pX, nullptr, nullptr,
            LTOK, HDIM, MHID, MH_P, HDIM, HDIM);
    }

    // merger
    rmsnorm_kernel<<<LTOK, 256>>>(pX, pRES, lnq_w, nullptr, nH, nL);
    // m0 (split-K S=4 into pM0, then standalone gelu+split)
    cudaMemsetAsync(pM0, 0, (long)LMERG * H4 * sizeof(float));
    tcgemm_kernel<E_BIAS><<<ggrid(LMERG, H4, 4), GT, GEMM_SMEM>>>(
        nH, nL, m0H, m0L, m0_b, nullptr, pM0, nullptr, nullptr,
        LMERG, H4, H4, H4, H4, H4);
    gelu_split_kernel<<<16384, 256>>>(pM0, aH, aL, (long)LMERG * H4 / 4);
    // m2 (split-K S=4 into d_out)
    cudaMemsetAsync(d_out, 0, (long)out_size * sizeof(float));
    tcgemm_kernel<E_BIAS><<<ggrid(LMERG, DMODEL, 4), GT, GEMM_SMEM>>>(
        aH, aL, m2H, m2L, m2_b, nullptr, (float*)d_out, nullptr, nullptr,
        LMERG, DMODEL, H4, H4, DMODEL, DMODEL);
}

// round 14
// speedup vs baseline: 1.0128x; 1.0128x over previous
#include <cuda_runtime.h>
#include <cuda_bf16.h>
#include <math.h>
#include <stdint.h>

// ---------------- problem constants ----------------
#define LTOK 8192
#define HDIM 1280
#define NHEAD 16
#define HEADD 80
#define MHID 3420
#define MH_P 3424
#define GU_N 6848          // interleaved gate|up width (2 * MH_P)
#define NBLK 4
#define NWIN 128
#define PDIM 1176
#define DMODEL 3584
#define H4 5120
#define LMERG 2048

// ---------------- fp32 scratch ----------------
static constexpr long SZ_LH  = (long)LTOK * HDIM;
static constexpr long SZ_L3H = (long)LTOK * 3 * HDIM;

static constexpr long F_X    = 0;
static constexpr long F_RES  = F_X   + SZ_LH;
static constexpr long F_HB   = F_RES + SZ_LH;
static constexpr long F_QKV  = F_HB  + SZ_LH;
static constexpr long F_M0   = F_QKV + SZ_L3H;           // merger m0 out [LMERG][H4]
static constexpr long F_TOTAL = F_M0 + (long)LMERG * H4;
__device__ float g_f32[F_TOTAL];

__device__ float g_bias[NBLK * GU_N];

// ---------------- bf16 scratch (hi/lo pairs) ----------------
static constexpr long SZ_XS  = (long)LTOK * PDIM;
static constexpr long SZ_PW  = (long)PDIM * HDIM;
static constexpr long SZ_QW  = (long)NBLK * HDIM * 3*HDIM;
static constexpr long SZ_PRW = (long)NBLK * HDIM * HDIM;
static constexpr long SZ_GU  = (long)NBLK * HDIM * GU_N;
static constexpr long SZ_DW  = (long)NBLK * MHID * HDIM;
static constexpr long SZ_M0W = (long)H4 * H4;
static constexpr long SZ_M2W = (long)H4 * DMODEL;
static constexpr long SZ_SHP = (long)LTOK * MH_P;

static constexpr long B_XH  = 0;
static constexpr long B_XL  = B_XH + SZ_XS;
static constexpr long B_NH  = B_XL + SZ_XS;
static constexpr long B_NL  = B_NH + SZ_LH;
static constexpr long B_AH  = B_NL + SZ_LH;
static constexpr long B_AL  = B_AH + SZ_LH;
static constexpr long B_SH  = B_AL + SZ_LH;
static constexpr long B_SL  = B_SH + SZ_SHP;
static constexpr long B_PW  = B_SL + SZ_SHP;
static constexpr long B_QW  = B_PW + 2*SZ_PW;
static constexpr long B_PRW = B_QW + 2*SZ_QW;
static constexpr long B_GUH = B_PRW + 2*SZ_PRW;
static constexpr long B_GUL = B_GUH + SZ_GU;
static constexpr long B_DW  = B_GUL + SZ_GU;
static constexpr long B_M0W = B_DW + 2*SZ_DW;
static constexpr long B_M2W = B_M0W + 2*SZ_M0W;
static constexpr long B_TOTAL = B_M2W + 2*SZ_M2W;
__device__ __nv_bfloat16 g_bf16[B_TOTAL];

// ---------------- PTX helpers (base sm_103 target only!) ----------------
__device__ __forceinline__ uint32_t smem_to_u32(const void* p) {
    uint32_t a;
    asm("{ .reg .u64 t; cvta.to.shared.u64 t, %1; cvt.u32.u64 %0, t; }" : "=r"(a) : "l"(p));
    return a;
}
__device__ __forceinline__ void cp16(uint32_t dst, const void* src, int bytes) {
    asm volatile("cp.async.cg.shared.global [%0], [%1], 16, %2;"
                 :: "r"(dst), "l"(src), "r"(bytes));
}
#define CP_COMMIT() asm volatile("cp.async.commit_group;" ::: "memory")
#define CP_WAIT2()  asm volatile("cp.async.wait_group 2;" ::: "memory")

__device__ __forceinline__ void ldsm_x4(uint32_t r[4], uint32_t addr) {
    asm volatile("ldmatrix.sync.aligned.m8n8.x4.shared.b16 {%0,%1,%2,%3}, [%4];"
                 : "=r"(r[0]), "=r"(r[1]), "=r"(r[2]), "=r"(r[3]) : "r"(addr));
}
__device__ __forceinline__ void ldsm_x4t(uint32_t r[4], uint32_t addr) {
    asm volatile("ldmatrix.sync.aligned.m8n8.x4.trans.shared.b16 {%0,%1,%2,%3}, [%4];"
                 : "=r"(r[0]), "=r"(r[1]), "=r"(r[2]), "=r"(r[3]) : "r"(addr));
}
__device__ __forceinline__ void mma_bf16(float c[4], const uint32_t a[4],
                                         uint32_t b0, uint32_t b1) {
    asm volatile(
        "mma.sync.aligned.m16n8k16.row.col.f32.bf16.bf16.f32 "
        "{%0,%1,%2,%3}, {%4,%5,%6,%7}, {%8,%9}, {%0,%1,%2,%3};"
        : "+f"(c[0]), "+f"(c[1]), "+f"(c[2]), "+f"(c[3])
        : "r"(a[0]), "r"(a[1]), "r"(a[2]), "r"(a[3]), "r"(b0), "r"(b1));
}

// ---------------- tensor-core GEMM (bf16x3 split, fp32 accum, optional split-K) ----------------
enum { E_NONE = 0, E_BIAS = 1, E_BIAS_RES = 2, E_SWIGLU = 3 };

#define A_STRIDE 40
#define B_STRIDE 136
#define A_TILE_B (128 * A_STRIDE * 2)      // 10240
#define B_TILE_B (32 * B_STRIDE * 2)       // 8704
#define STAGE_B  (2 * A_TILE_B + 2 * B_TILE_B)  // 37888
#define OFF_AH 0
#define OFF_AL A_TILE_B
#define OFF_BH (2 * A_TILE_B)
#define OFF_BL (2 * A_TILE_B + B_TILE_B)
#define GEMM_SMEM (3 * STAGE_B)            // 113664
#define GT 256

template<int EPI>
__global__ void __launch_bounds__(GT, 2) tcgemm_kernel(
    const __nv_bfloat16* __restrict__ Ah, const __nv_bfloat16* __restrict__ Al,
    const __nv_bfloat16* __restrict__ Bh, const __nv_bfloat16* __restrict__ Bl,
    const float* __restrict__ bias, const float* __restrict__ res,
    float* __restrict__ C, __nv_bfloat16* __restrict__ Oh, __nv_bfloat16* __restrict__ Ol,
    int M, int N, int K, int lda, int ldb, int ldc)
{
    extern __shared__ __align__(16) char sm[];
    const uint32_t smem_u = smem_to_u32(sm);
    const int tid = threadIdx.x;
    const int lane = tid & 31, wid = tid >> 5;
    const int wm = wid >> 2, wn = wid & 3;
    const int row0 = blockIdx.y * 128, col0 = blockIdx.x * 128;

    const int nc_tot = (K + 31) / 32;
    const int S = gridDim.z;
    const int per = (nc_tot + S - 1) / S;
    const int c0 = blockIdx.z * per;
    int c1 = c0 + per; if (c1 > nc_tot) c1 = nc_tot;
    const int myn = (c1 > c0) ? (c1 - c0) : 0;

    auto load_stage = [&](int st, int c) {
        const uint32_t sbase = smem_u + st * STAGE_B;
        const int k0 = c * 32;
        #pragma unroll
        for (int h = 0; h < 2; ++h) {
            const __nv_bfloat16* src = h ? Al : Ah;
            const uint32_t dbase = sbase + (h ? OFF_AL : OFF_AH);
            #pragma unroll
            for (int it = 0; it < 2; ++it) {
                int e = tid + it * 256;
                int r = e >> 2, q = e & 3;
                int gr = row0 + r;
                int gk = k0 + q * 8;
                int bytes = (K - gk) * 2;
                bytes = bytes < 0 ? 0 : (bytes > 16 ? 16 : bytes);
                const __nv_bfloat16* g = src + (long)gr * lda + (bytes > 0 ? gk : 0);
                cp16(dbase + r * (A_STRIDE * 2) + q * 16, g, bytes);
            }
        }
        #pragma unroll
        for (int h = 0; h < 2; ++h) {
            const __nv_bfloat16* src = h ? Bl : Bh;
            const uint32_t dbase = sbase + (h ? OFF_BL : OFF_BH);
            #pragma unroll
            for (int it = 0; it < 2; ++it) {
                int e = tid + it * 256;
                int r = e >> 4, q = e & 15;
                int gk = k0 + r;
                int gc = col0 + q * 8;
                int bytes = (N - gc) * 2;
                bytes = bytes < 0 ? 0 : (bytes > 16 ? 16 : bytes);
                if (gk >= K) bytes = 0;
                const __nv_bfloat16* g = src + (long)(gk < K ? gk : 0) * ldb + (bytes > 0 ? gc : 0);
                cp16(dbase + r * (B_STRIDE * 2) + q * 16, g, bytes);
            }
        }
    };

    const int a_row = lane & 15;
    const int a_kh = (lane >> 4) * 8;
    const int b_g = lane >> 3, b_l = lane & 7;
    const int b_k = (b_g & 1) * 8 + b_l;
    const int b_n = (b_g >> 1) * 8;

    float acc[4][4][4];
    #pragma unroll
    for (int i = 0; i < 4; ++i)
        #pragma unroll
        for (int j = 0; j < 4; ++j)
            #pragma unroll
            for (int r = 0; r < 4; ++r) acc[i][j][r] = 0.f;

    #pragma unroll
    for (int s = 0; s < 3; ++s) {
        if (s < myn) load_stage(s, c0 + s);
        CP_COMMIT();
    }

    for (int cc = 0; cc < myn; ++cc) {
        CP_WAIT2();
        __syncthreads();
        const int st = cc % 3;
        const uint32_t sbase = smem_u + st * STAGE_B;
        const uint32_t aB[2] = { sbase + OFF_AH, sbase + OFF_AL };
        const uint32_t bB[2] = { sbase + OFF_BH, sbase + OFF_BL };

        #pragma unroll
        for (int ks = 0; ks < 2; ++ks) {
            uint32_t af[2][4][4];
            #pragma unroll
            for (int h = 0; h < 2; ++h)
                #pragma unroll
                for (int i = 0; i < 4; ++i)
                    ldsm_x4(af[h][i],
                        aB[h] + 2u * ((wm * 64 + i * 16 + a_row) * A_STRIDE + ks * 16 + a_kh));
            #pragma unroll
            for (int j2 = 0; j2 < 2; ++j2) {
                uint32_t b0[4], b1[4];
                uint32_t boff = 2u * ((ks * 16 + b_k) * B_STRIDE + wn * 32 + j2 * 16 + b_n);
                ldsm_x4t(b0, bB[0] + boff);
                ldsm_x4t(b1, bB[1] + boff);
                #pragma unroll
                for (int i = 0; i < 4; ++i) {
                    mma_bf16(acc[i][2*j2],   af[0][i], b0[0], b0[1]);
                    mma_bf16(acc[i][2*j2+1], af[0][i], b0[2], b0[3]);
                    mma_bf16(acc[i][2*j2],   af[0][i], b1[0], b1[1]);
                    mma_bf16(acc[i][2*j2+1], af[0][i], b1[2], b1[3]);
                    mma_bf16(acc[i][2*j2],   af[1][i], b0[0], b0[1]);
                    mma_bf16(acc[i][2*j2+1], af[1][i], b0[2], b0[3]);
                }
            }
        }
        __syncthreads();
        if (cc + 3 < myn) load_stage(st, c0 + cc + 3);
        CP_COMMIT();
    }

    const bool add_const = (blockIdx.z == 0);
    const int g = lane >> 2, t = lane & 3;
    #pragma unroll
    for (int i = 0; i < 4; ++i) {
        #pragma unroll
        for (int j = 0; j < 4; ++j) {
            int col = col0 + wn * 32 + j * 8 + t * 2;
            if (col >= N) continue;
            float b0 = 0.f, b1 = 0.f;
            if (EPI != E_NONE && add_const) { b0 = bias[col]; b1 = bias[col + 1]; }
            #pragma unroll
            for (int rr = 0; rr < 2; ++rr) {
                int row = row0 + wm * 64 + i * 16 + g + rr * 8;
                if (row >= M) continue;
                float v0 = acc[i][j][rr * 2 + 0] + b0;
                float v1 = acc[i][j][rr * 2 + 1] + b1;
                if (EPI == E_SWIGLU) {
                    // interleaved layout: v0 = gate_j, v1 = up_j, j = col/2
                    float sw = v0 / (1.f + __expf(-v0)) * v1;
                    __nv_bfloat16 hh = __float2bfloat16(sw);
                    long oidx = (long)row * MH_P + (col >> 1);
                    Oh[oidx] = hh;
                    Ol[oidx] = __float2bfloat16(sw - __bfloat162float(hh));
                    continue;
                }
                long idx = (long)row * ldc + col;
                if (EPI == E_BIAS_RES && add_const) { v0 += res[idx]; v1 += res[idx + 1]; }
                if (gridDim.z == 1) {
                    *reinterpret_cast<float2*>(C + idx) = make_float2(v0, v1);
                } else {
                    atomicAdd(C + idx, v0);
                    atomicAdd(C + idx + 1, v1);
                }
            }
        }
    }
}

// ---------------- fused windowed attention with inline RoPE (fp32) ----------------
#define SP 81
#define ATTN_SMEM (3 * 64 * SP * 4)

__global__ void __launch_bounds__(256) attn_kernel(
    const float* __restrict__ qkv, const float* __restrict__ cosb,
    const float* __restrict__ sinb, __nv_bfloat16* __restrict__ outH,
    __nv_bfloat16* __restrict__ outL)
{
    extern __shared__ float smf[];
    float* q = smf;
    float* k = smf + 64 * SP;
    float* v = smf + 2 * 64 * SP;
    float* s = smf;                 // aliases q (dead after QK phase)

    const int w = blockIdx.x >> 4;
    const int h = blockIdx.x & 15;
    const int tid = threadIdx.x;
    const float scale = 0.11180339887498949f;

    for (int e = tid; e < 64 * 80; e += 256) {
        int t = e / 80, j = e % 80;
        int l = w * 64 + t;
        long base = (long)l * (3 * HDIM) + h * 80;
        float c = cosb[l * 80 + j], sn = sinb[l * 80 + j];
        float qv = qkv[base + j];
        float qr = (j < 40) ? -qkv[base + j + 40] : qkv[base + j - 40];
        q[t * SP + j] = qv * c + qr * sn;
        float kv = qkv[base + HDIM + j];
        float kr = (j < 40) ? -qkv[base + HDIM + j + 40] : qkv[base + HDIM + j - 40];
        k[t * SP + j] = kv * c + kr * sn;
        v[t * SP + j] = qkv[base + 2 * HDIM + j];
    }
    __syncthreads();

    {
        const int tx = tid & 15, ty = tid >> 4;
        float acc[4][4] = {};
        for (int d = 0; d < 80; d++) {
            float qa[4], kb[4];
            #pragma unroll
            for (int i = 0; i < 4; i++) qa[i] = q[(ty * 4 + i) * SP + d];
            #pragma unroll
            for (int j = 0; j < 4; j++) kb[j] = k[(tx * 4 + j) * SP + d];
            #pragma unroll
            for (int i = 0; i < 4; i++)
                #pragma unroll
                for (int j = 0; j < 4; j++)
                    acc[i][j] += qa[i] * kb[j];
        }
        __syncthreads();
        #pragma unroll
        for (int i = 0; i < 4; i++)
            #pragma unroll
            for (int j = 0; j < 4; j++)
                s[(ty * 4 + i) * 64 + tx * 4 + j] = acc[i][j] * scale;
    }
    __syncthreads();

    {
        const int warp = tid >> 5, lane = tid & 31;
        for (int r = warp; r < 64; r += 8) {
            float x0 = s[r * 64 + lane], x1 = s[r * 64 + 32 + lane];
            float mx = fmaxf(x0, x1);
            #pragma unroll
            for (int o = 16; o > 0; o >>= 1) mx = fmaxf(mx, __shfl_xor_sync(~0u, mx, o));
            float e0 = __expf(x0 - mx), e1 = __expf(x1 - mx);
            float sum = e0 + e1;
            #pragma unroll
            for (int o = 16; o > 0; o >>= 1) sum += __shfl_xor_sync(~0u, sum, o);
            float inv = 1.f / sum;
            s[r * 64 + lane] = e0 * inv;
            s[r * 64 + 32 + lane] = e1 * inv;
        }
    }
    __syncthreads();

    {
        const int tx = tid & 15, ty = tid >> 4;
        float acc[4][5] = {};
        for (int kk = 0; kk < 64; kk++) {
            float sa[4], vb[5];
            #pragma unroll
            for (int i = 0; i < 4; i++) sa[i] = s[(ty * 4 + i) * 64 + kk];
            #pragma unroll
            for (int j = 0; j < 5; j++) vb[j] = v[kk * SP + tx * 5 + j];
            #pragma unroll
            for (int i = 0; i < 4; i++)
                #pragma unroll
                for (int j = 0; j < 5; j++)
                    acc[i][j] += sa[i] * vb[j];
        }
        #pragma unroll
        for (int i = 0; i < 4; i++) {
            long obase = (long)(w * 64 + ty * 4 + i) * HDIM + h * 80 + tx * 5;
            #pragma unroll
            for (int j = 0; j < 5; j++) {
                float val = acc[i][j];
                __nv_bfloat16 hh = __float2bfloat16(val);
                outH[obase + j] = hh;
                outL[obase + j] = __float2bfloat16(val - __bfloat162float(hh));
            }
        }
    }
}

// ---------------- fused (optional add) + RMSNorm, bf16 hi/lo out ----------------
__global__ void __launch_bounds__(256) rmsnorm_kernel(
    const float* __restrict__ a, const float* __restrict__ b,
    const float* __restrict__ w, float* __restrict__ sum_out,
    __nv_bfloat16* __restrict__ nh, __nv_bfloat16* __restrict__ nl)
{
    __shared__ float sv[HDIM];
    __shared__ float red[8];
    __shared__ float s_scale;
    const int row = blockIdx.x, tid = threadIdx.x;
    const long base = (long)row * HDIM;
    float ss = 0.f;
    for (int j = tid; j < HDIM; j += 256) {
        float v = a[base + j];
        if (b) v += b[base + j];
        sv[j] = v;
        if (sum_out) sum_out[base + j] = v;
        ss += v * v;
    }
    #pragma unroll
    for (int o = 16; o > 0; o >>= 1) ss += __shfl_xor_sync(~0u, ss, o);
    if ((tid & 31) == 0) red[tid >> 5] = ss;
    __syncthreads();
    if (tid == 0) {
        float t = 0.f;
        #pragma unroll
        for (int i = 0; i < 8; i++) t += red[i];
        s_scale = rsqrtf(t / (float)HDIM + 1e-6f);
    }
    __syncthreads();
    float sc = s_scale;
    for (int j = tid; j < HDIM; j += 256) {
        float v = sv[j] * sc * w[j];
        __nv_bfloat16 hh = __float2bfloat16(v);
        nh[base + j] = hh;
        nl[base + j] = __float2bfloat16(v - __bfloat162float(hh));
    }
}

// ---------------- standalone GELU + bf16 hi/lo split (for split-K m0) ----------------
__global__ void __launch_bounds__(256) gelu_split_kernel(
    const float* __restrict__ in, __nv_bfloat16* __restrict__ oh,
    __nv_bfloat16* __restrict__ ol, long n4)
{
    for (long i = (long)blockIdx.x * 256 + threadIdx.x; i < n4; i += (long)gridDim.x * 256) {
        float4 v = *reinterpret_cast<const float4*>(in + 4 * i);
        float vv[4] = {v.x, v.y, v.z, v.w};
        __nv_bfloat16 th[4], tl[4];
        #pragma unroll
        for (int j = 0; j < 4; j++) {
            float x = vv[j];
            float g = 0.5f * x * (1.f + erff(x * 0.70710678118654752f));
            __nv_bfloat16 hh = __float2bfloat16(g);
            th[j] = hh;
            tl[j] = __float2bfloat16(g - __bfloat162float(hh));
        }
        *reinterpret_cast<uint2*>(oh + 4 * i) = *reinterpret_cast<uint2*>(th);
        *reinterpret_cast<uint2*>(ol + 4 * i) = *reinterpret_cast<uint2*>(tl);
    }
}

// ---------------- interleaved gate|up weight split: out[r][2j]=gate, out[r][2j+1]=up ----------------
__global__ void __launch_bounds__(256) split_interleave_kernel(
    const float* __restrict__ gw, const float* __restrict__ uw,
    __nv_bfloat16* __restrict__ h, __nv_bfloat16* __restrict__ l, int rows)
{
    const int j4n = MH_P / 4;     // 856
    long total = (long)rows * j4n;
    for (long i = (long)blockIdx.x * 256 + threadIdx.x; i < total; i += (long)gridDim.x * 256) {
        int r = (int)(i / j4n);
        int j0 = (int)(i - (long)r * j4n) * 4;
        __nv_bfloat16 th[8], tl[8];
        #pragma unroll
        for (int jj = 0; jj < 4; ++jj) {
            int j = j0 + jj;
            float gv = (j < MHID) ? gw[(long)r * MHID + j] : 0.f;
            float uv = (j < MHID) ? uw[(long)r * MHID + j] : 0.f;
            __nv_bfloat16 gh = __float2bfloat16(gv);
            __nv_bfloat16 uh = __float2bfloat16(uv);
            th[2*jj]   = gh;
            th[2*jj+1] = uh;
            tl[2*jj]   = __float2bfloat16(gv - __bfloat162float(gh));
            tl[2*jj+1] = __float2bfloat16(uv - __bfloat162float(uh));
        }
        long o = (long)r * GU_N + 2 * j0;
        *reinterpret_cast<uint4*>(h + o) = *reinterpret_cast<uint4*>(th);
        *reinterpret_cast<uint4*>(l + o) = *reinterpret_cast<uint4*>(tl);
    }
}

// ---------------- interleaved gate|up bias fill ----------------
__global__ void __launch_bounds__(256) fill_bias_kernel(
    const float* __restrict__ gate_b, const float* __restrict__ up_b, float* __restrict__ out)
{
    int i = blockIdx.x * 256 + threadIdx.x;
    if (i >= NBLK * GU_N) return;
    int d = i / GU_N, c = i - d * GU_N;
    int j = c >> 1;
    float v = 0.f;
    if (j < MHID) v = (c & 1) ? up_b[d * MHID + j] : gate_b[d * MHID + j];
    out[i] = v;
}

// ---------------- fp32 -> bf16 hi/lo splits ----------------
__global__ void __launch_bounds__(256) split_kernel(
    const float4* __restrict__ in, __nv_bfloat16* __restrict__ h,
    __nv_bfloat16* __restrict__ l, long n4)
{
    for (long i = (long)blockIdx.x * 256 + threadIdx.x; i < n4; i += (long)gridDim.x * 256) {
        float4 v = in[i];
        __nv_bfloat16 th[4], tl[4];
        float vv[4] = {v.x, v.y, v.z, v.w};
        #pragma unroll
        for (int j = 0; j < 4; j++) {
            th[j] = __float2bfloat16(vv[j]);
            tl[j] = __float2bfloat16(vv[j] - __bfloat162float(th[j]));
        }
        *reinterpret_cast<uint2*>(h + 4 * i) = *reinterpret_cast<uint2*>(th);
        *reinterpret_cast<uint2*>(l + 4 * i) = *reinterpret_cast<uint2*>(tl);
    }
}

// ---------------- host ----------------
static inline dim3 ggrid(int M, int N, int S = 1) {
    return dim3((N + 127) / 128, (M + 127) / 128, S);
}

static inline void do_split(const float* src, __nv_bfloat16* h, __nv_bfloat16* l, long n) {
    long n4 = n / 4;
    int blocks = (int)((n4 + 255) / 256);
    if (blocks > 16384) blocks = 16384;
    split_kernel<<<blocks, 256>>>((const float4*)src, h, l, n4);
}

extern "C" void kernel_launch(void* const* d_in, const int* in_sizes, int n_in,
                              void* d_out, int out_size)
{
    const float* x       = (const float*)d_in[0];
    const float* cosb    = (const float*)d_in[1];
    const float* sinb    = (const float*)d_in[2];
    const float* patch_w = (const float*)d_in[3];
    const float* norm1_w = (const float*)d_in[4];
    const float* norm2_w = (const float*)d_in[5];
    const float* qkv_w   = (const float*)d_in[6];
    const float* qkv_b   = (const float*)d_in[7];
    const float* proj_w  = (const float*)d_in[8];
    const float* proj_b  = (const float*)d_in[9];
    const float* gate_w  = (const float*)d_in[10];
    const float* gate_b  = (const float*)d_in[11];
    const float* up_w    = (const float*)d_in[12];
    const float* up_b    = (const float*)d_in[13];
    const float* down_w  = (const float*)d_in[14];
    const float* down_b  = (const float*)d_in[15];
    const float* lnq_w   = (const float*)d_in[16];
    const float* m0_w    = (const float*)d_in[17];
    const float* m0_b    = (const float*)d_in[18];
    const float* m2_w    = (const float*)d_in[19];
    const float* m2_b    = (const float*)d_in[20];

    float* fs = nullptr;
    __nv_bfloat16* bs = nullptr;
    float* gub = nullptr;
    cudaGetSymbolAddress((void**)&fs, g_f32);
    cudaGetSymbolAddress((void**)&bs, g_bf16);
    cudaGetSymbolAddress((void**)&gub, g_bias);

    float* pX    = fs + F_X;
    float* pRES  = fs + F_RES;
    float* pHB   = fs + F_HB;
    float* pQKV  = fs + F_QKV;
    float* pM0   = fs + F_M0;

    __nv_bfloat16 *xH = bs+B_XH, *xL = bs+B_XL;
    __nv_bfloat16 *nH = bs+B_NH, *nL = bs+B_NL;
    __nv_bfloat16 *aH = bs+B_AH, *aL = bs+B_AL;
    __nv_bfloat16 *sH = bs+B_SH, *sL = bs+B_SL;
    __nv_bfloat16 *pwH = bs+B_PW,  *pwL = pwH + SZ_PW;
    __nv_bfloat16 *qwH = bs+B_QW,  *qwL = qwH + SZ_QW;
    __nv_bfloat16 *prH = bs+B_PRW, *prL = prH + SZ_PRW;
    __nv_bfloat16 *guH = bs+B_GUH, *guL = bs+B_GUL;
    __nv_bfloat16 *dwH = bs+B_DW,  *dwL = dwH + SZ_DW;
    __nv_bfloat16 *m0H = bs+B_M0W, *m0L = m0H + SZ_M0W;
    __nv_bfloat16 *m2H = bs+B_M2W, *m2L = m2H + SZ_M2W;

    cudaFuncSetAttribute(tcgemm_kernel<E_NONE>, cudaFuncAttributeMaxDynamicSharedMemorySize, GEMM_SMEM);
    cudaFuncSetAttribute(tcgemm_kernel<E_BIAS>, cudaFuncAttributeMaxDynamicSharedMemorySize, GEMM_SMEM);
    cudaFuncSetAttribute(tcgemm_kernel<E_BIAS_RES>, cudaFuncAttributeMaxDynamicSharedMemorySize, GEMM_SMEM);
    cudaFuncSetAttribute(tcgemm_kernel<E_SWIGLU>, cudaFuncAttributeMaxDynamicSharedMemorySize, GEMM_SMEM);
    cudaFuncSetAttribute(attn_kernel, cudaFuncAttributeMaxDynamicSharedMemorySize, ATTN_SMEM);

    do_split(x,       xH,  xL,  SZ_XS);
    do_split(patch_w, pwH, pwL, SZ_PW);
    do_split(qkv_w,   qwH, qwL, SZ_QW);
    do_split(proj_w,  prH, prL, SZ_PRW);
    split_interleave_kernel<<<16384, 256>>>(gate_w, up_w, guH, guL, NBLK * HDIM);

    // patch embed (split-K S=4, atomic)
    cudaMemsetAsync(pX, 0, SZ_LH * sizeof(float));
    tcgemm_kernel<E_NONE><<<ggrid(LTOK, HDIM, 4), GT, GEMM_SMEM>>>(
        xH, xL, pwH, pwL, nullptr, nullptr, pX, nullptr, nullptr,
        LTOK, HDIM, PDIM, PDIM, HDIM, HDIM);

    do_split(down_w,  dwH, dwL, SZ_DW);
    do_split(m0_w,    m0H, m0L, SZ_M0W);
    do_split(m2_w,    m2H, m2L, SZ_M2W);
    fill_bias_kernel<<<(NBLK * GU_N + 255) / 256, 256>>>(gate_b, up_b, gub);

    for (int d = 0; d < NBLK; d++) {
        rmsnorm_kernel<<<LTOK, 256>>>(pX, d == 0 ? nullptr : pRES,
                                      norm1_w + (long)d * HDIM, pHB, nH, nL);
        // qkv (S=1, plain store — big output, split-K hurts here)
        tcgemm_kernel<E_BIAS><<<ggrid(LTOK, 3 * HDIM), GT, GEMM_SMEM>>>(
            nH, nL, qwH + (long)d * HDIM * 3 * HDIM, qwL + (long)d * HDIM * 3 * HDIM,
            qkv_b + (long)d * 3 * HDIM, nullptr, pQKV, nullptr, nullptr,
            LTOK, 3 * HDIM, HDIM, HDIM, 3 * HDIM, 3 * HDIM);
        attn_kernel<<<NWIN * NHEAD, 256, ATTN_SMEM>>>(pQKV, cosb, sinb, aH, aL);
        // proj + residual (split-K S=4, atomic; bias+res added by z=0)
        cudaMemsetAsync(pRES, 0, SZ_LH * sizeof(float));
        tcgemm_kernel<E_BIAS_RES><<<ggrid(LTOK, HDIM, 4), GT, GEMM_SMEM>>>(
            aH, aL, prH + (long)d * HDIM * HDIM, prL + (long)d * HDIM * HDIM,
            proj_b + (long)d * HDIM, pHB, pRES, nullptr, nullptr,
            LTOK, HDIM, HDIM, HDIM, HDIM, HDIM);
        rmsnorm_kernel<<<LTOK, 256>>>(pRES, nullptr, norm2_w + (long)d * HDIM, nullptr, nH, nL);
        // merged interleaved gate|up GEMM with fused swiglu epilogue -> sH/sL
        tcgemm_kernel<E_SWIGLU><<<ggrid(LTOK, GU_N), GT, GEMM_SMEM>>>(
            nH, nL, guH + (long)d * HDIM * GU_N, guL + (long)d * HDIM * GU_N,
            gub + (long)d * GU_N, nullptr, nullptr, sH, sL,
            LTOK, GU_N, HDIM, HDIM, GU_N, GU_N);
        // down (split-K S=4, atomic)
        cudaMemsetAsync(pX, 0, SZ_LH * sizeof(float));
        tcgemm_kernel<E_BIAS><<<ggrid(LTOK, HDIM, 4), GT, GEMM_SMEM>>>(
            sH, sL, dwH + (long)d * MHID * HDIM, dwL + (long)d * MHID * HDIM,
            down_b + (long)d * HDIM, nullptr, pX, nullptr, nullptr,
            LTOK, HDIM, MHID, MH_P, HDIM, HDIM);
    }

    // merger
    rmsnorm_kernel<<<LTOK, 256>>>(pX, pRES, lnq_w, nullptr, nH, nL);
    // m0 (split-K S=4 into pM0, then standalone gelu+split)
    cudaMemsetAsync(pM0, 0, (long)LMERG * H4 * sizeof(float));
    tcgemm_kernel<E_BIAS><<<ggrid(LMERG, H4, 4), GT, GEMM_SMEM>>>(
        nH, nL, m0H, m0L, m0_b, nullptr, pM0, nullptr, nullptr,
        LMERG, H4, H4, H4, H4, H4);
    gelu_split_kernel<<<16384, 256>>>(pM0, aH, aL, (long)LMERG * H4 / 4);
    // m2 (split-K S=4 into d_out)
    cudaMemsetAsync(d_out, 0, (long)out_size * sizeof(float));
    tcgemm_kernel<E_BIAS><<<ggrid(LMERG, DMODEL, 4), GT, GEMM_SMEM>>>(
        aH, aL, m2H, m2L, m2_b, nullptr, (float*)d_out, nullptr, nullptr,
        LMERG, DMODEL, H4, H4, DMODEL, DMODEL);
}

// round 15
// speedup vs baseline: 1.0168x; 1.0040x over previous
#include <cuda_runtime.h>
#include <cuda_bf16.h>
#include <math.h>
#include <stdint.h>

// ---------------- problem constants ----------------
#define LTOK 8192
#define HDIM 1280
#define NHEAD 16
#define HEADD 80
#define MHID 3420
#define MH_P 3424
#define GU_N 6848          // interleaved gate|up width (2 * MH_P)
#define NBLK 4
#define NWIN 128
#define PDIM 1176
#define DMODEL 3584
#define H4 5120
#define LMERG 2048

// ---------------- fp32 scratch ----------------
static constexpr long SZ_LH  = (long)LTOK * HDIM;
static constexpr long SZ_L3H = (long)LTOK * 3 * HDIM;

static constexpr long F_X    = 0;
static constexpr long F_RES  = F_X   + SZ_LH;
static constexpr long F_HB   = F_RES + SZ_LH;
static constexpr long F_QKV  = F_HB  + SZ_LH;
static constexpr long F_M0   = F_QKV + SZ_L3H;           // merger m0 out [LMERG][H4]
static constexpr long F_TOTAL = F_M0 + (long)LMERG * H4;
__device__ float g_f32[F_TOTAL];

__device__ float g_bias[NBLK * GU_N];

// ---------------- bf16 scratch (hi/lo pairs) ----------------
static constexpr long SZ_XS  = (long)LTOK * PDIM;
static constexpr long SZ_PW  = (long)PDIM * HDIM;
static constexpr long SZ_QW  = (long)NBLK * HDIM * 3*HDIM;
static constexpr long SZ_PRW = (long)NBLK * HDIM * HDIM;
static constexpr long SZ_GU  = (long)NBLK * HDIM * GU_N;
static constexpr long SZ_DW  = (long)NBLK * MHID * HDIM;
static constexpr long SZ_M0W = (long)H4 * H4;
static constexpr long SZ_M2W = (long)H4 * DMODEL;
static constexpr long SZ_SHP = (long)LTOK * MH_P;

static constexpr long B_XH  = 0;
static constexpr long B_XL  = B_XH + SZ_XS;
static constexpr long B_NH  = B_XL + SZ_XS;
static constexpr long B_NL  = B_NH + SZ_LH;
static constexpr long B_AH  = B_NL + SZ_LH;
static constexpr long B_AL  = B_AH + SZ_LH;
static constexpr long B_SH  = B_AL + SZ_LH;
static constexpr long B_SL  = B_SH + SZ_SHP;
static constexpr long B_PW  = B_SL + SZ_SHP;
static constexpr long B_QW  = B_PW + 2*SZ_PW;
static constexpr long B_PRW = B_QW + 2*SZ_QW;
static constexpr long B_GUH = B_PRW + 2*SZ_PRW;
static constexpr long B_GUL = B_GUH + SZ_GU;
static constexpr long B_DW  = B_GUL + SZ_GU;
static constexpr long B_M0W = B_DW + 2*SZ_DW;
static constexpr long B_M2W = B_M0W + 2*SZ_M0W;
static constexpr long B_TOTAL = B_M2W + 2*SZ_M2W;
__device__ __nv_bfloat16 g_bf16[B_TOTAL];

// ---------------- PTX helpers (base sm_103 target only!) ----------------
__device__ __forceinline__ uint32_t smem_to_u32(const void* p) {
    uint32_t a;
    asm("{ .reg .u64 t; cvta.to.shared.u64 t, %1; cvt.u32.u64 %0, t; }" : "=r"(a) : "l"(p));
    return a;
}
__device__ __forceinline__ void cp16(uint32_t dst, const void* src, int bytes) {
    asm volatile("cp.async.cg.shared.global [%0], [%1], 16, %2;"
                 :: "r"(dst), "l"(src), "r"(bytes));
}
#define CP_COMMIT() asm volatile("cp.async.commit_group;" ::: "memory")
#define CP_WAIT2()  asm volatile("cp.async.wait_group 2;" ::: "memory")

__device__ __forceinline__ void ldsm_x4(uint32_t r[4], uint32_t addr) {
    asm volatile("ldmatrix.sync.aligned.m8n8.x4.shared.b16 {%0,%1,%2,%3}, [%4];"
                 : "=r"(r[0]), "=r"(r[1]), "=r"(r[2]), "=r"(r[3]) : "r"(addr));
}
__device__ __forceinline__ void ldsm_x4t(uint32_t r[4], uint32_t addr) {
    asm volatile("ldmatrix.sync.aligned.m8n8.x4.trans.shared.b16 {%0,%1,%2,%3}, [%4];"
                 : "=r"(r[0]), "=r"(r[1]), "=r"(r[2]), "=r"(r[3]) : "r"(addr));
}
__device__ __forceinline__ void mma_bf16(float c[4], const uint32_t a[4],
                                         uint32_t b0, uint32_t b1) {
    asm volatile(
        "mma.sync.aligned.m16n8k16.row.col.f32.bf16.bf16.f32 "
        "{%0,%1,%2,%3}, {%4,%5,%6,%7}, {%8,%9}, {%0,%1,%2,%3};"
        : "+f"(c[0]), "+f"(c[1]), "+f"(c[2]), "+f"(c[3])
        : "r"(a[0]), "r"(a[1]), "r"(a[2]), "r"(a[3]), "r"(b0), "r"(b1));
}

// ---------------- tensor-core GEMM (bf16x3 split, fp32 accum, optional split-K) ----------------
enum { E_NONE = 0, E_BIAS = 1, E_BIAS_RES = 2, E_SWIGLU = 3 };

#define A_STRIDE 40
#define B_STRIDE 136
#define A_TILE_B (128 * A_STRIDE * 2)      // 10240
#define B_TILE_B (32 * B_STRIDE * 2)       // 8704
#define STAGE_B  (2 * A_TILE_B + 2 * B_TILE_B)  // 37888
#define OFF_AH 0
#define OFF_AL A_TILE_B
#define OFF_BH (2 * A_TILE_B)
#define OFF_BL (2 * A_TILE_B + B_TILE_B)
#define GEMM_SMEM (3 * STAGE_B)            // 113664
#define GT 256

template<int EPI>
__global__ void __launch_bounds__(GT, 2) tcgemm_kernel(
    const __nv_bfloat16* __restrict__ Ah, const __nv_bfloat16* __restrict__ Al,
    const __nv_bfloat16* __restrict__ Bh, const __nv_bfloat16* __restrict__ Bl,
    const float* __restrict__ bias, const float* __restrict__ res,
    float* __restrict__ C, __nv_bfloat16* __restrict__ Oh, __nv_bfloat16* __restrict__ Ol,
    int M, int N, int K, int lda, int ldb, int ldc)
{
    extern __shared__ __align__(16) char sm[];
    const uint32_t smem_u = smem_to_u32(sm);
    const int tid = threadIdx.x;
    const int lane = tid & 31, wid = tid >> 5;
    const int wm = wid >> 2, wn = wid & 3;
    const int row0 = blockIdx.y * 128, col0 = blockIdx.x * 128;

    const int nc_tot = (K + 31) / 32;
    const int S = gridDim.z;
    const int per = (nc_tot + S - 1) / S;
    const int c0 = blockIdx.z * per;
    int c1 = c0 + per; if (c1 > nc_tot) c1 = nc_tot;
    const int myn = (c1 > c0) ? (c1 - c0) : 0;

    auto load_stage = [&](int st, int c) {
        const uint32_t sbase = smem_u + st * STAGE_B;
        const int k0 = c * 32;
        #pragma unroll
        for (int h = 0; h < 2; ++h) {
            const __nv_bfloat16* src = h ? Al : Ah;
            const uint32_t dbase = sbase + (h ? OFF_AL : OFF_AH);
            #pragma unroll
            for (int it = 0; it < 2; ++it) {
                int e = tid + it * 256;
                int r = e >> 2, q = e & 3;
                int gr = row0 + r;
                int gk = k0 + q * 8;
                int bytes = (K - gk) * 2;
                bytes = bytes < 0 ? 0 : (bytes > 16 ? 16 : bytes);
                const __nv_bfloat16* g = src + (long)gr * lda + (bytes > 0 ? gk : 0);
                cp16(dbase + r * (A_STRIDE * 2) + q * 16, g, bytes);
            }
        }
        #pragma unroll
        for (int h = 0; h < 2; ++h) {
            const __nv_bfloat16* src = h ? Bl : Bh;
            const uint32_t dbase = sbase + (h ? OFF_BL : OFF_BH);
            #pragma unroll
            for (int it = 0; it < 2; ++it) {
                int e = tid + it * 256;
                int r = e >> 4, q = e & 15;
                int gk = k0 + r;
                int gc = col0 + q * 8;
                int bytes = (N - gc) * 2;
                bytes = bytes < 0 ? 0 : (bytes > 16 ? 16 : bytes);
                if (gk >= K) bytes = 0;
                const __nv_bfloat16* g = src + (long)(gk < K ? gk : 0) * ldb + (bytes > 0 ? gc : 0);
                cp16(dbase + r * (B_STRIDE * 2) + q * 16, g, bytes);
            }
        }
    };

    const int a_row = lane & 15;
    const int a_kh = (lane >> 4) * 8;
    const int b_g = lane >> 3, b_l = lane & 7;
    const int b_k = (b_g & 1) * 8 + b_l;
    const int b_n = (b_g >> 1) * 8;

    float acc[4][4][4];
    #pragma unroll
    for (int i = 0; i < 4; ++i)
        #pragma unroll
        for (int j = 0; j < 4; ++j)
            #pragma unroll
            for (int r = 0; r < 4; ++r) acc[i][j][r] = 0.f;

    #pragma unroll
    for (int s = 0; s < 3; ++s) {
        if (s < myn) load_stage(s, c0 + s);
        CP_COMMIT();
    }

    for (int cc = 0; cc < myn; ++cc) {
        CP_WAIT2();
        __syncthreads();
        const int st = cc % 3;
        const uint32_t sbase = smem_u + st * STAGE_B;
        const uint32_t aB[2] = { sbase + OFF_AH, sbase + OFF_AL };
        const uint32_t bB[2] = { sbase + OFF_BH, sbase + OFF_BL };

        #pragma unroll
        for (int ks = 0; ks < 2; ++ks) {
            uint32_t af[2][4][4];
            #pragma unroll
            for (int h = 0; h < 2; ++h)
                #pragma unroll
                for (int i = 0; i < 4; ++i)
                    ldsm_x4(af[h][i],
                        aB[h] + 2u * ((wm * 64 + i * 16 + a_row) * A_STRIDE + ks * 16 + a_kh));
            #pragma unroll
            for (int j2 = 0; j2 < 2; ++j2) {
                uint32_t b0[4], b1[4];
                uint32_t boff = 2u * ((ks * 16 + b_k) * B_STRIDE + wn * 32 + j2 * 16 + b_n);
                ldsm_x4t(b0, bB[0] + boff);
                ldsm_x4t(b1, bB[1] + boff);
                #pragma unroll
                for (int i = 0; i < 4; ++i) {
                    mma_bf16(acc[i][2*j2],   af[0][i], b0[0], b0[1]);
                    mma_bf16(acc[i][2*j2+1], af[0][i], b0[2], b0[3]);
                    mma_bf16(acc[i][2*j2],   af[0][i], b1[0], b1[1]);
                    mma_bf16(acc[i][2*j2+1], af[0][i], b1[2], b1[3]);
                    mma_bf16(acc[i][2*j2],   af[1][i], b0[0], b0[1]);
                    mma_bf16(acc[i][2*j2+1], af[1][i], b0[2], b0[3]);
                }
            }
        }
        __syncthreads();
        if (cc + 3 < myn) load_stage(st, c0 + cc + 3);
        CP_COMMIT();
    }

    const bool add_const = (blockIdx.z == 0);
    const int g = lane >> 2, t = lane & 3;
    #pragma unroll
    for (int i = 0; i < 4; ++i) {
        #pragma unroll
        for (int j = 0; j < 4; ++j) {
            int col = col0 + wn * 32 + j * 8 + t * 2;
            if (col >= N) continue;
            float b0 = 0.f, b1 = 0.f;
            if (EPI != E_NONE && add_const) { b0 = bias[col]; b1 = bias[col + 1]; }
            #pragma unroll
            for (int rr = 0; rr < 2; ++rr) {
                int row = row0 + wm * 64 + i * 16 + g + rr * 8;
                if (row >= M) continue;
                float v0 = acc[i][j][rr * 2 + 0] + b0;
                float v1 = acc[i][j][rr * 2 + 1] + b1;
                if (EPI == E_SWIGLU) {
                    // interleaved layout: v0 = gate_j, v1 = up_j, j = col/2
                    float sw = v0 / (1.f + __expf(-v0)) * v1;
                    __nv_bfloat16 hh = __float2bfloat16(sw);
                    long oidx = (long)row * MH_P + (col >> 1);
                    Oh[oidx] = hh;
                    Ol[oidx] = __float2bfloat16(sw - __bfloat162float(hh));
                    continue;
                }
                long idx = (long)row * ldc + col;
                if (EPI == E_BIAS_RES && add_const) { v0 += res[idx]; v1 += res[idx + 1]; }
                if (gridDim.z == 1) {
                    *reinterpret_cast<float2*>(C + idx) = make_float2(v0, v1);
                } else {
                    atomicAdd(C + idx, v0);
                    atomicAdd(C + idx + 1, v1);
                }
            }
        }
    }
}

// ---------------- fused windowed attention with inline RoPE (fp32) ----------------
// Q/K stored TRANSPOSED in smem (qT[d][token], row stride 68) so the QK inner
// loop reads one float4 (4 consecutive tokens) per operand per d — 4x fewer LDS.
// Score buffer aliases qT (dead after QK). 64.3KB smem -> still 3 CTAs/SM.
#define SPT 68
#define SPV 81
#define ATTN_SMEM ((2 * 80 * SPT + 64 * SPV) * 4)

__global__ void __launch_bounds__(256) attn_kernel(
    const float* __restrict__ qkv, const float* __restrict__ cosb,
    const float* __restrict__ sinb, __nv_bfloat16* __restrict__ outH,
    __nv_bfloat16* __restrict__ outL)
{
    extern __shared__ float smf[];
    float* qT = smf;                  // [80][68]
    float* kT = smf + 80 * SPT;       // [80][68]
    float* v  = smf + 2 * 80 * SPT;   // [64][81]
    float* s  = smf;                  // aliases qT (dead after QK phase)

    const int w = blockIdx.x >> 4;
    const int h = blockIdx.x & 15;
    const int tid = threadIdx.x;
    const float scale = 0.11180339887498949f;

    for (int e = tid; e < 64 * 80; e += 256) {
        int t = e / 80, j = e % 80;
        int l = w * 64 + t;
        long base = (long)l * (3 * HDIM) + h * 80;
        float c = cosb[l * 80 + j], sn = sinb[l * 80 + j];
        float qv = qkv[base + j];
        float qr = (j < 40) ? -qkv[base + j + 40] : qkv[base + j - 40];
        qT[j * SPT + t] = qv * c + qr * sn;
        float kv = qkv[base + HDIM + j];
        float kr = (j < 40) ? -qkv[base + HDIM + j + 40] : qkv[base + HDIM + j - 40];
        kT[j * SPT + t] = kv * c + kr * sn;
        v[t * SPV + j] = qkv[base + 2 * HDIM + j];
    }
    __syncthreads();

    {
        const int tx = tid & 15, ty = tid >> 4;
        float acc[4][4] = {};
        for (int d = 0; d < 80; d++) {
            float4 qa = *reinterpret_cast<const float4*>(&qT[d * SPT + ty * 4]);
            float4 kb = *reinterpret_cast<const float4*>(&kT[d * SPT + tx * 4]);
            float qv[4] = {qa.x, qa.y, qa.z, qa.w};
            float kv[4] = {kb.x, kb.y, kb.z, kb.w};
            #pragma unroll
            for (int i = 0; i < 4; i++)
                #pragma unroll
                for (int j = 0; j < 4; j++)
                    acc[i][j] += qv[i] * kv[j];
        }
        __syncthreads();   // all reads of qT complete before s overwrites it
        #pragma unroll
        for (int i = 0; i < 4; i++) {
            float4 sv = make_float4(acc[i][0] * scale, acc[i][1] * scale,
                                    acc[i][2] * scale, acc[i][3] * scale);
            *reinterpret_cast<float4*>(&s[(ty * 4 + i) * 64 + tx * 4]) = sv;
        }
    }
    __syncthreads();

    {
        const int warp = tid >> 5, lane = tid & 31;
        for (int r = warp; r < 64; r += 8) {
            float x0 = s[r * 64 + lane], x1 = s[r * 64 + 32 + lane];
            float mx = fmaxf(x0, x1);
            #pragma unroll
            for (int o = 16; o > 0; o >>= 1) mx = fmaxf(mx, __shfl_xor_sync(~0u, mx, o));
            float e0 = __expf(x0 - mx), e1 = __expf(x1 - mx);
            float sum = e0 + e1;
            #pragma unroll
            for (int o = 16; o > 0; o >>= 1) sum += __shfl_xor_sync(~0u, sum, o);
            float inv = 1.f / sum;
            s[r * 64 + lane] = e0 * inv;
            s[r * 64 + 32 + lane] = e1 * inv;
        }
    }
    __syncthreads();

    {
        const int tx = tid & 15, ty = tid >> 4;
        float acc[4][5] = {};
        for (int kk = 0; kk < 64; kk++) {
            float sa[4], vb[5];
            #pragma unroll
            for (int i = 0; i < 4; i++) sa[i] = s[(ty * 4 + i) * 64 + kk];
            #pragma unroll
            for (int j = 0; j < 5; j++) vb[j] = v[kk * SPV + tx * 5 + j];
            #pragma unroll
            for (int i = 0; i < 4; i++)
                #pragma unroll
                for (int j = 0; j < 5; j++)
                    acc[i][j] += sa[i] * vb[j];
        }
        #pragma unroll
        for (int i = 0; i < 4; i++) {
            long obase = (long)(w * 64 + ty * 4 + i) * HDIM + h * 80 + tx * 5;
            #pragma unroll
            for (int j = 0; j < 5; j++) {
                float val = acc[i][j];
                __nv_bfloat16 hh = __float2bfloat16(val);
                outH[obase + j] = hh;
                outL[obase + j] = __float2bfloat16(val - __bfloat162float(hh));
            }
        }
    }
}

// ---------------- fused (optional add) + RMSNorm, bf16 hi/lo out ----------------
__global__ void __launch_bounds__(256) rmsnorm_kernel(
    const float* __restrict__ a, const float* __restrict__ b,
    const float* __restrict__ w, float* __restrict__ sum_out,
    __nv_bfloat16* __restrict__ nh, __nv_bfloat16* __restrict__ nl)
{
    __shared__ float sv[HDIM];
    __shared__ float red[8];
    __shared__ float s_scale;
    const int row = blockIdx.x, tid = threadIdx.x;
    const long base = (long)row * HDIM;
    float ss = 0.f;
    for (int j = tid; j < HDIM; j += 256) {
        float v = a[base + j];
        if (b) v += b[base + j];
        sv[j] = v;
        if (sum_out) sum_out[base + j] = v;
        ss += v * v;
    }
    #pragma unroll
    for (int o = 16; o > 0; o >>= 1) ss += __shfl_xor_sync(~0u, ss, o);
    if ((tid & 31) == 0) red[tid >> 5] = ss;
    __syncthreads();
    if (tid == 0) {
        float t = 0.f;
        #pragma unroll
        for (int i = 0; i < 8; i++) t += red[i];
        s_scale = rsqrtf(t / (float)HDIM + 1e-6f);
    }
    __syncthreads();
    float sc = s_scale;
    for (int j = tid; j < HDIM; j += 256) {
        float v = sv[j] * sc * w[j];
        __nv_bfloat16 hh = __float2bfloat16(v);
        nh[base + j] = hh;
        nl[base + j] = __float2bfloat16(v - __bfloat162float(hh));
    }
}

// ---------------- standalone GELU + bf16 hi/lo split (for split-K m0) ----------------
__global__ void __launch_bounds__(256) gelu_split_kernel(
    const float* __restrict__ in, __nv_bfloat16* __restrict__ oh,
    __nv_bfloat16* __restrict__ ol, long n4)
{
    for (long i = (long)blockIdx.x * 256 + threadIdx.x; i < n4; i += (long)gridDim.x * 256) {
        float4 v = *reinterpret_cast<const float4*>(in + 4 * i);
        float vv[4] = {v.x, v.y, v.z, v.w};
        __nv_bfloat16 th[4], tl[4];
        #pragma unroll
        for (int j = 0; j < 4; j++) {
            float x = vv[j];
            float g = 0.5f * x * (1.f + erff(x * 0.70710678118654752f));
            __nv_bfloat16 hh = __float2bfloat16(g);
            th[j] = hh;
            tl[j] = __float2bfloat16(g - __bfloat162float(hh));
        }
        *reinterpret_cast<uint2*>(oh + 4 * i) = *reinterpret_cast<uint2*>(th);
        *reinterpret_cast<uint2*>(ol + 4 * i) = *reinterpret_cast<uint2*>(tl);
    }
}

// ---------------- interleaved gate|up weight split: out[r][2j]=gate, out[r][2j+1]=up ----------------
__global__ void __launch_bounds__(256) split_interleave_kernel(
    const float* __restrict__ gw, const float* __restrict__ uw,
    __nv_bfloat16* __restrict__ h, __nv_bfloat16* __restrict__ l, int rows)
{
    const int j4n = MH_P / 4;     // 856
    long total = (long)rows * j4n;
    for (long i = (long)blockIdx.x * 256 + threadIdx.x; i < total; i += (long)gridDim.x * 256) {
        int r = (int)(i / j4n);
        int j0 = (int)(i - (long)r * j4n) * 4;
        __nv_bfloat16 th[8], tl[8];
        #pragma unroll
        for (int jj = 0; jj < 4; ++jj) {
            int j = j0 + jj;
            float gv = (j < MHID) ? gw[(long)r * MHID + j] : 0.f;
            float uv = (j < MHID) ? uw[(long)r * MHID + j] : 0.f;
            __nv_bfloat16 gh = __float2bfloat16(gv);
            __nv_bfloat16 uh = __float2bfloat16(uv);
            th[2*jj]   = gh;
            th[2*jj+1] = uh;
            tl[2*jj]   = __float2bfloat16(gv - __bfloat162float(gh));
            tl[2*jj+1] = __float2bfloat16(uv - __bfloat162float(uh));
        }
        long o = (long)r * GU_N + 2 * j0;
        *reinterpret_cast<uint4*>(h + o) = *reinterpret_cast<uint4*>(th);
        *reinterpret_cast<uint4*>(l + o) = *reinterpret_cast<uint4*>(tl);
    }
}

// ---------------- interleaved gate|up bias fill ----------------
__global__ void __launch_bounds__(256) fill_bias_kernel(
    const float* __restrict__ gate_b, const float* __restrict__ up_b, float* __restrict__ out)
{
    int i = blockIdx.x * 256 + threadIdx.x;
    if (i >= NBLK * GU_N) return;
    int d = i / GU_N, c = i - d * GU_N;
    int j = c >> 1;
    float v = 0.f;
    if (j < MHID) v = (c & 1) ? up_b[d * MHID + j] : gate_b[d * MHID + j];
    out[i] = v;
}

// ---------------- fp32 -> bf16 hi/lo splits ----------------
__global__ void __launch_bounds__(256) split_kernel(
    const float4* __restrict__ in, __nv_bfloat16* __restrict__ h,
    __nv_bfloat16* __restrict__ l, long n4)
{
    for (long i = (long)blockIdx.x * 256 + threadIdx.x; i < n4; i += (long)gridDim.x * 256) {
        float4 v = in[i];
        __nv_bfloat16 th[4], tl[4];
        float vv[4] = {v.x, v.y, v.z, v.w};
        #pragma unroll
        for (int j = 0; j < 4; j++) {
            th[j] = __float2bfloat16(vv[j]);
            tl[j] = __float2bfloat16(vv[j] - __bfloat162float(th[j]));
        }
        *reinterpret_cast<uint2*>(h + 4 * i) = *reinterpret_cast<uint2*>(th);
        *reinterpret_cast<uint2*>(l + 4 * i) = *reinterpret_cast<uint2*>(tl);
    }
}

// ---------------- host ----------------
static inline dim3 ggrid(int M, int N, int S = 1) {
    return dim3((N + 127) / 128, (M + 127) / 128, S);
}

static inline void do_split(const float* src, __nv_bfloat16* h, __nv_bfloat16* l, long n) {
    long n4 = n / 4;
    int blocks = (int)((n4 + 255) / 256);
    if (blocks > 16384) blocks = 16384;
    split_kernel<<<blocks, 256>>>((const float4*)src, h, l, n4);
}

extern "C" void kernel_launch(void* const* d_in, const int* in_sizes, int n_in,
                              void* d_out, int out_size)
{
    const float* x       = (const float*)d_in[0];
    const float* cosb    = (const float*)d_in[1];
    const float* sinb    = (const float*)d_in[2];
    const float* patch_w = (const float*)d_in[3];
    const float* norm1_w = (const float*)d_in[4];
    const float* norm2_w = (const float*)d_in[5];
    const float* qkv_w   = (const float*)d_in[6];
    const float* qkv_b   = (const float*)d_in[7];
    const float* proj_w  = (const float*)d_in[8];
    const float* proj_b  = (const float*)d_in[9];
    const float* gate_w  = (const float*)d_in[10];
    const float* gate_b  = (const float*)d_in[11];
    const float* up_w    = (const float*)d_in[12];
    const float* up_b    = (const float*)d_in[13];
    const float* down_w  = (const float*)d_in[14];
    const float* down_b  = (const float*)d_in[15];
    const float* lnq_w   = (const float*)d_in[16];
    const float* m0_w    = (const float*)d_in[17];
    const float* m0_b    = (const float*)d_in[18];
    const float* m2_w    = (const float*)d_in[19];
    const float* m2_b    = (const float*)d_in[20];

    float* fs = nullptr;
    __nv_bfloat16* bs = nullptr;
    float* gub = nullptr;
    cudaGetSymbolAddress((void**)&fs, g_f32);
    cudaGetSymbolAddress((void**)&bs, g_bf16);
    cudaGetSymbolAddress((void**)&gub, g_bias);

    float* pX    = fs + F_X;
    float* pRES  = fs + F_RES;
    float* pHB   = fs + F_HB;
    float* pQKV  = fs + F_QKV;
    float* pM0   = fs + F_M0;

    __nv_bfloat16 *xH = bs+B_XH, *xL = bs+B_XL;
    __nv_bfloat16 *nH = bs+B_NH, *nL = bs+B_NL;
    __nv_bfloat16 *aH = bs+B_AH, *aL = bs+B_AL;
    __nv_bfloat16 *sH = bs+B_SH, *sL = bs+B_SL;
    __nv_bfloat16 *pwH = bs+B_PW,  *pwL = pwH + SZ_PW;
    __nv_bfloat16 *qwH = bs+B_QW,  *qwL = qwH + SZ_QW;
    __nv_bfloat16 *prH = bs+B_PRW, *prL = prH + SZ_PRW;
    __nv_bfloat16 *guH = bs+B_GUH, *guL = bs+B_GUL;
    __nv_bfloat16 *dwH = bs+B_DW,  *dwL = dwH + SZ_DW;
    __nv_bfloat16 *m0H = bs+B_M0W, *m0L = m0H + SZ_M0W;
    __nv_bfloat16 *m2H = bs+B_M2W, *m2L = m2H + SZ_M2W;

    cudaFuncSetAttribute(tcgemm_kernel<E_NONE>, cudaFuncAttributeMaxDynamicSharedMemorySize, GEMM_SMEM);
    cudaFuncSetAttribute(tcgemm_kernel<E_BIAS>, cudaFuncAttributeMaxDynamicSharedMemorySize, GEMM_SMEM);
    cudaFuncSetAttribute(tcgemm_kernel<E_BIAS_RES>, cudaFuncAttributeMaxDynamicSharedMemorySize, GEMM_SMEM);
    cudaFuncSetAttribute(tcgemm_kernel<E_SWIGLU>, cudaFuncAttributeMaxDynamicSharedMemorySize, GEMM_SMEM);
    cudaFuncSetAttribute(attn_kernel, cudaFuncAttributeMaxDynamicSharedMemorySize, ATTN_SMEM);

    do_split(x,       xH,  xL,  SZ_XS);
    do_split(patch_w, pwH, pwL, SZ_PW);
    do_split(qkv_w,   qwH, qwL, SZ_QW);
    do_split(proj_w,  prH, prL, SZ_PRW);
    split_interleave_kernel<<<16384, 256>>>(gate_w, up_w, guH, guL, NBLK * HDIM);

    // patch embed (split-K S=4, atomic)
    cudaMemsetAsync(pX, 0, SZ_LH * sizeof(float));
    tcgemm_kernel<E_NONE><<<ggrid(LTOK, HDIM, 4), GT, GEMM_SMEM>>>(
        xH, xL, pwH, pwL, nullptr, nullptr, pX, nullptr, nullptr,
        LTOK, HDIM, PDIM, PDIM, HDIM, HDIM);

    do_split(down_w,  dwH, dwL, SZ_DW);
    do_split(m0_w,    m0H, m0L, SZ_M0W);
    do_split(m2_w,    m2H, m2L, SZ_M2W);
    fill_bias_kernel<<<(NBLK * GU_N + 255) / 256, 256>>>(gate_b, up_b, gub);

    for (int d = 0; d < NBLK; d++) {
        rmsnorm_kernel<<<LTOK, 256>>>(pX, d == 0 ? nullptr : pRES,
                                      norm1_w + (long)d * HDIM, pHB, nH, nL);
        // qkv (S=1, plain store — big output, split-K hurts here)
        tcgemm_kernel<E_BIAS><<<ggrid(LTOK, 3 * HDIM), GT, GEMM_SMEM>>>(
            nH, nL, qwH + (long)d * HDIM * 3 * HDIM, qwL + (long)d * HDIM * 3 * HDIM,
            qkv_b + (long)d * 3 * HDIM, nullptr, pQKV, nullptr, nullptr,
            LTOK, 3 * HDIM, HDIM, HDIM, 3 * HDIM, 3 * HDIM);
        attn_kernel<<<NWIN * NHEAD, 256, ATTN_SMEM>>>(pQKV, cosb, sinb, aH, aL);
        // proj + residual (split-K S=4, atomic; bias+res added by z=0)
        cudaMemsetAsync(pRES, 0, SZ_LH * sizeof(float));
        tcgemm_kernel<E_BIAS_RES><<<ggrid(LTOK, HDIM, 4), GT, GEMM_SMEM>>>(
            aH, aL, prH + (long)d * HDIM * HDIM, prL + (long)d * HDIM * HDIM,
            proj_b + (long)d * HDIM, pHB, pRES, nullptr, nullptr,
            LTOK, HDIM, HDIM, HDIM, HDIM, HDIM);
        rmsnorm_kernel<<<LTOK, 256>>>(pRES, nullptr, norm2_w + (long)d * HDIM, nullptr, nH, nL);
        // merged interleaved gate|up GEMM with fused swiglu epilogue -> sH/sL
        tcgemm_kernel<E_SWIGLU><<<ggrid(LTOK, GU_N), GT, GEMM_SMEM>>>(
            nH, nL, guH + (long)d * HDIM * GU_N, guL + (long)d * HDIM * GU_N,
            gub + (long)d * GU_N, nullptr, nullptr, sH, sL,
            LTOK, GU_N, HDIM, HDIM, GU_N, GU_N);
        // down (split-K S=4, atomic)
        cudaMemsetAsync(pX, 0, SZ_LH * sizeof(float));
        tcgemm_kernel<E_BIAS><<<ggrid(LTOK, HDIM, 4), GT, GEMM_SMEM>>>(
            sH, sL, dwH + (long)d * MHID * HDIM, dwL + (long)d * MHID * HDIM,
            down_b + (long)d * HDIM, nullptr, pX, nullptr, nullptr,
            LTOK, HDIM, MHID, MH_P, HDIM, HDIM);
    }

    // merger
    rmsnorm_kernel<<<LTOK, 256>>>(pX, pRES, lnq_w, nullptr, nH, nL);
    // m0 (split-K S=4 into pM0, then standalone gelu+split)
    cudaMemsetAsync(pM0, 0, (long)LMERG * H4 * sizeof(float));
    tcgemm_kernel<E_BIAS><<<ggrid(LMERG, H4, 4), GT, GEMM_SMEM>>>(
        nH, nL, m0H, m0L, m0_b, nullptr, pM0, nullptr, nullptr,
        LMERG, H4, H4, H4, H4, H4);
    gelu_split_kernel<<<16384, 256>>>(pM0, aH, aL, (long)LMERG * H4 / 4);
    // m2 (split-K S=4 into d_out)
    cudaMemsetAsync(d_out, 0, (long)out_size * sizeof(float));
    tcgemm_kernel<E_BIAS><<<ggrid(LMERG, DMODEL, 4), GT, GEMM_SMEM>>>(
        aH, aL, m2H, m2L, m2_b, nullptr, (float*)d_out, nullptr, nullptr,
        LMERG, DMODEL, H4, H4, DMODEL, DMODEL);
}

// round 16
// speedup vs baseline: 1.0282x; 1.0111x over previous
#include <cuda_runtime.h>
#include <cuda_bf16.h>
#include <math.h>
#include <stdint.h>

// ---------------- problem constants ----------------
#define LTOK 8192
#define HDIM 1280
#define NHEAD 16
#define HEADD 80
#define MHID 3420
#define MH_P 3424
#define GU_N 6848          // interleaved gate|up width (2 * MH_P)
#define NBLK 4
#define NWIN 128
#define PDIM 1176
#define DMODEL 3584
#define H4 5120
#define LMERG 2048

// ---------------- fp32 scratch ----------------
static constexpr long SZ_LH  = (long)LTOK * HDIM;
static constexpr long SZ_L3H = (long)LTOK * 3 * HDIM;

static constexpr long F_X    = 0;
static constexpr long F_RES  = F_X   + SZ_LH;
static constexpr long F_HB   = F_RES + SZ_LH;
static constexpr long F_QKV  = F_HB  + SZ_LH;
static constexpr long F_M0   = F_QKV + SZ_L3H;           // merger m0 out [LMERG][H4]
static constexpr long F_TOTAL = F_M0 + (long)LMERG * H4;
__device__ float g_f32[F_TOTAL];

__device__ float g_bias[NBLK * GU_N];

// ---------------- bf16 scratch (hi/lo pairs) ----------------
static constexpr long SZ_XS  = (long)LTOK * PDIM;
static constexpr long SZ_PW  = (long)PDIM * HDIM;
static constexpr long SZ_QW  = (long)NBLK * HDIM * 3*HDIM;
static constexpr long SZ_PRW = (long)NBLK * HDIM * HDIM;
static constexpr long SZ_GU  = (long)NBLK * HDIM * GU_N;
static constexpr long SZ_DW  = (long)NBLK * MHID * HDIM;
static constexpr long SZ_M0W = (long)H4 * H4;
static constexpr long SZ_M2W = (long)H4 * DMODEL;
static constexpr long SZ_SHP = (long)LTOK * MH_P;

static constexpr long B_XH  = 0;
static constexpr long B_XL  = B_XH + SZ_XS;
static constexpr long B_NH  = B_XL + SZ_XS;
static constexpr long B_NL  = B_NH + SZ_LH;
static constexpr long B_AH  = B_NL + SZ_LH;
static constexpr long B_AL  = B_AH + SZ_LH;
static constexpr long B_SH  = B_AL + SZ_LH;
static constexpr long B_SL  = B_SH + SZ_SHP;
static constexpr long B_PW  = B_SL + SZ_SHP;
static constexpr long B_QW  = B_PW + 2*SZ_PW;
static constexpr long B_PRW = B_QW + 2*SZ_QW;
static constexpr long B_GUH = B_PRW + 2*SZ_PRW;
static constexpr long B_GUL = B_GUH + SZ_GU;
static constexpr long B_DW  = B_GUL + SZ_GU;
static constexpr long B_M0W = B_DW + 2*SZ_DW;
static constexpr long B_M2W = B_M0W + 2*SZ_M0W;
static constexpr long B_TOTAL = B_M2W + 2*SZ_M2W;
__device__ __nv_bfloat16 g_bf16[B_TOTAL];

// ---------------- PTX helpers (base sm_103 target only!) ----------------
__device__ __forceinline__ uint32_t smem_to_u32(const void* p) {
    uint32_t a;
    asm("{ .reg .u64 t; cvta.to.shared.u64 t, %1; cvt.u32.u64 %0, t; }" : "=r"(a) : "l"(p));
    return a;
}
__device__ __forceinline__ void cp16(uint32_t dst, const void* src, int bytes) {
    asm volatile("cp.async.cg.shared.global [%0], [%1], 16, %2;"
                 :: "r"(dst), "l"(src), "r"(bytes));
}
#define CP_COMMIT() asm volatile("cp.async.commit_group;" ::: "memory")
#define CP_WAIT2()  asm volatile("cp.async.wait_group 2;" ::: "memory")

__device__ __forceinline__ void ldsm_x4(uint32_t r[4], uint32_t addr) {
    asm volatile("ldmatrix.sync.aligned.m8n8.x4.shared.b16 {%0,%1,%2,%3}, [%4];"
                 : "=r"(r[0]), "=r"(r[1]), "=r"(r[2]), "=r"(r[3]) : "r"(addr));
}
__device__ __forceinline__ void ldsm_x4t(uint32_t r[4], uint32_t addr) {
    asm volatile("ldmatrix.sync.aligned.m8n8.x4.trans.shared.b16 {%0,%1,%2,%3}, [%4];"
                 : "=r"(r[0]), "=r"(r[1]), "=r"(r[2]), "=r"(r[3]) : "r"(addr));
}
__device__ __forceinline__ void mma_bf16(float c[4], const uint32_t a[4],
                                         uint32_t b0, uint32_t b1) {
    asm volatile(
        "mma.sync.aligned.m16n8k16.row.col.f32.bf16.bf16.f32 "
        "{%0,%1,%2,%3}, {%4,%5,%6,%7}, {%8,%9}, {%0,%1,%2,%3};"
        : "+f"(c[0]), "+f"(c[1]), "+f"(c[2]), "+f"(c[3])
        : "r"(a[0]), "r"(a[1]), "r"(a[2]), "r"(a[3]), "r"(b0), "r"(b1));
}

// ---------------- tensor-core GEMM (bf16x3 split, fp32 accum, optional split-K) ----------------
enum { E_NONE = 0, E_BIAS = 1, E_BIAS_RES = 2, E_SWIGLU = 3 };

#define A_STRIDE 40
#define B_STRIDE 136
#define A_TILE_B (128 * A_STRIDE * 2)      // 10240
#define B_TILE_B (32 * B_STRIDE * 2)       // 8704
#define STAGE_B  (2 * A_TILE_B + 2 * B_TILE_B)  // 37888
#define OFF_AH 0
#define OFF_AL A_TILE_B
#define OFF_BH (2 * A_TILE_B)
#define OFF_BL (2 * A_TILE_B + B_TILE_B)
#define GEMM_SMEM (3 * STAGE_B)            // 113664
#define GT 256

template<int EPI>
__global__ void __launch_bounds__(GT, 2) tcgemm_kernel(
    const __nv_bfloat16* __restrict__ Ah, const __nv_bfloat16* __restrict__ Al,
    const __nv_bfloat16* __restrict__ Bh, const __nv_bfloat16* __restrict__ Bl,
    const float* __restrict__ bias, const float* __restrict__ res,
    float* __restrict__ C, __nv_bfloat16* __restrict__ Oh, __nv_bfloat16* __restrict__ Ol,
    int M, int N, int K, int lda, int ldb, int ldc)
{
    extern __shared__ __align__(16) char sm[];
    const uint32_t smem_u = smem_to_u32(sm);
    const int tid = threadIdx.x;
    const int lane = tid & 31, wid = tid >> 5;
    const int wm = wid >> 2, wn = wid & 3;
    const int row0 = blockIdx.y * 128, col0 = blockIdx.x * 128;

    const int nc_tot = (K + 31) / 32;
    const int S = gridDim.z;
    const int per = (nc_tot + S - 1) / S;
    const int c0 = blockIdx.z * per;
    int c1 = c0 + per; if (c1 > nc_tot) c1 = nc_tot;
    const int myn = (c1 > c0) ? (c1 - c0) : 0;

    auto load_stage = [&](int st, int c) {
        const uint32_t sbase = smem_u + st * STAGE_B;
        const int k0 = c * 32;
        #pragma unroll
        for (int h = 0; h < 2; ++h) {
            const __nv_bfloat16* src = h ? Al : Ah;
            const uint32_t dbase = sbase + (h ? OFF_AL : OFF_AH);
            #pragma unroll
            for (int it = 0; it < 2; ++it) {
                int e = tid + it * 256;
                int r = e >> 2, q = e & 3;
                int gr = row0 + r;
                int gk = k0 + q * 8;
                int bytes = (K - gk) * 2;
                bytes = bytes < 0 ? 0 : (bytes > 16 ? 16 : bytes);
                const __nv_bfloat16* g = src + (long)gr * lda + (bytes > 0 ? gk : 0);
                cp16(dbase + r * (A_STRIDE * 2) + q * 16, g, bytes);
            }
        }
        #pragma unroll
        for (int h = 0; h < 2; ++h) {
            const __nv_bfloat16* src = h ? Bl : Bh;
            const uint32_t dbase = sbase + (h ? OFF_BL : OFF_BH);
            #pragma unroll
            for (int it = 0; it < 2; ++it) {
                int e = tid + it * 256;
                int r = e >> 4, q = e & 15;
                int gk = k0 + r;
                int gc = col0 + q * 8;
                int bytes = (N - gc) * 2;
                bytes = bytes < 0 ? 0 : (bytes > 16 ? 16 : bytes);
                if (gk >= K) bytes = 0;
                const __nv_bfloat16* g = src + (long)(gk < K ? gk : 0) * ldb + (bytes > 0 ? gc : 0);
                cp16(dbase + r * (B_STRIDE * 2) + q * 16, g, bytes);
            }
        }
    };

    const int a_row = lane & 15;
    const int a_kh = (lane >> 4) * 8;
    const int b_g = lane >> 3, b_l = lane & 7;
    const int b_k = (b_g & 1) * 8 + b_l;
    const int b_n = (b_g >> 1) * 8;

    float acc[4][4][4];
    #pragma unroll
    for (int i = 0; i < 4; ++i)
        #pragma unroll
        for (int j = 0; j < 4; ++j)
            #pragma unroll
            for (int r = 0; r < 4; ++r) acc[i][j][r] = 0.f;

    #pragma unroll
    for (int s = 0; s < 3; ++s) {
        if (s < myn) load_stage(s, c0 + s);
        CP_COMMIT();
    }

    for (int cc = 0; cc < myn; ++cc) {
        CP_WAIT2();
        __syncthreads();
        const int st = cc % 3;
        const uint32_t sbase = smem_u + st * STAGE_B;
        const uint32_t aB[2] = { sbase + OFF_AH, sbase + OFF_AL };
        const uint32_t bB[2] = { sbase + OFF_BH, sbase + OFF_BL };

        #pragma unroll
        for (int ks = 0; ks < 2; ++ks) {
            uint32_t af[2][4][4];
            #pragma unroll
            for (int h = 0; h < 2; ++h)
                #pragma unroll
                for (int i = 0; i < 4; ++i)
                    ldsm_x4(af[h][i],
                        aB[h] + 2u * ((wm * 64 + i * 16 + a_row) * A_STRIDE + ks * 16 + a_kh));
            #pragma unroll
            for (int j2 = 0; j2 < 2; ++j2) {
                uint32_t b0[4], b1[4];
                uint32_t boff = 2u * ((ks * 16 + b_k) * B_STRIDE + wn * 32 + j2 * 16 + b_n);
                ldsm_x4t(b0, bB[0] + boff);
                ldsm_x4t(b1, bB[1] + boff);
                #pragma unroll
                for (int i = 0; i < 4; ++i) {
                    mma_bf16(acc[i][2*j2],   af[0][i], b0[0], b0[1]);
                    mma_bf16(acc[i][2*j2+1], af[0][i], b0[2], b0[3]);
                    mma_bf16(acc[i][2*j2],   af[0][i], b1[0], b1[1]);
                    mma_bf16(acc[i][2*j2+1], af[0][i], b1[2], b1[3]);
                    mma_bf16(acc[i][2*j2],   af[1][i], b0[0], b0[1]);
                    mma_bf16(acc[i][2*j2+1], af[1][i], b0[2], b0[3]);
                }
            }
        }
        __syncthreads();
        if (cc + 3 < myn) load_stage(st, c0 + cc + 3);
        CP_COMMIT();
    }

    const bool add_const = (blockIdx.z == 0);
    const int g = lane >> 2, t = lane & 3;
    #pragma unroll
    for (int i = 0; i < 4; ++i) {
        #pragma unroll
        for (int j = 0; j < 4; ++j) {
            int col = col0 + wn * 32 + j * 8 + t * 2;
            if (col >= N) continue;
            float b0 = 0.f, b1 = 0.f;
            if (EPI != E_NONE && add_const) { b0 = bias[col]; b1 = bias[col + 1]; }
            #pragma unroll
            for (int rr = 0; rr < 2; ++rr) {
                int row = row0 + wm * 64 + i * 16 + g + rr * 8;
                if (row >= M) continue;
                float v0 = acc[i][j][rr * 2 + 0] + b0;
                float v1 = acc[i][j][rr * 2 + 1] + b1;
                if (EPI == E_SWIGLU) {
                    float sw = v0 / (1.f + __expf(-v0)) * v1;
                    __nv_bfloat16 hh = __float2bfloat16(sw);
                    long oidx = (long)row * MH_P + (col >> 1);
                    Oh[oidx] = hh;
                    Ol[oidx] = __float2bfloat16(sw - __bfloat162float(hh));
                    continue;
                }
                long idx = (long)row * ldc + col;
                if (EPI == E_BIAS_RES && add_const) { v0 += res[idx]; v1 += res[idx + 1]; }
                if (gridDim.z == 1) {
                    *reinterpret_cast<float2*>(C + idx) = make_float2(v0, v1);
                } else {
                    atomicAdd(C + idx, v0);
                    atomicAdd(C + idx + 1, v1);
                }
            }
        }
    }
}

// ---------------- fused windowed attention with inline RoPE (fp32) ----------------
// Q/K transposed in smem; score buffer aliases qT; output staged in smem and
// written as coalesced uint4 rows. 64.3KB smem -> 3 CTAs/SM.
#define SPT 68
#define SPV 81
#define ATTN_SMEM ((2 * 80 * SPT + 64 * SPV) * 4)

__global__ void __launch_bounds__(256) attn_kernel(
    const float* __restrict__ qkv, const float* __restrict__ cosb,
    const float* __restrict__ sinb, __nv_bfloat16* __restrict__ outH,
    __nv_bfloat16* __restrict__ outL)
{
    extern __shared__ float smf[];
    float* qT = smf;                  // [80][68]
    float* kT = smf + 80 * SPT;       // [80][68]
    float* v  = smf + 2 * 80 * SPT;   // [64][81]
    float* s  = smf;                  // aliases qT (dead after QK phase)
    // output staging (after PV reads of s complete): 64x80 bf16 x2 = 20480B
    __nv_bfloat16* stH = reinterpret_cast<__nv_bfloat16*>(smf);
    __nv_bfloat16* stL = stH + 64 * 80;

    const int w = blockIdx.x >> 4;
    const int h = blockIdx.x & 15;
    const int tid = threadIdx.x;
    const float scale = 0.11180339887498949f;

    for (int e = tid; e < 64 * 80; e += 256) {
        int t = e / 80, j = e % 80;
        int l = w * 64 + t;
        long base = (long)l * (3 * HDIM) + h * 80;
        float c = cosb[l * 80 + j], sn = sinb[l * 80 + j];
        float qv = qkv[base + j];
        float qr = (j < 40) ? -qkv[base + j + 40] : qkv[base + j - 40];
        qT[j * SPT + t] = qv * c + qr * sn;
        float kv = qkv[base + HDIM + j];
        float kr = (j < 40) ? -qkv[base + HDIM + j + 40] : qkv[base + HDIM + j - 40];
        kT[j * SPT + t] = kv * c + kr * sn;
        v[t * SPV + j] = qkv[base + 2 * HDIM + j];
    }
    __syncthreads();

    {
        const int tx = tid & 15, ty = tid >> 4;
        float acc[4][4] = {};
        for (int d = 0; d < 80; d++) {
            float4 qa = *reinterpret_cast<const float4*>(&qT[d * SPT + ty * 4]);
            float4 kb = *reinterpret_cast<const float4*>(&kT[d * SPT + tx * 4]);
            float qv[4] = {qa.x, qa.y, qa.z, qa.w};
            float kv[4] = {kb.x, kb.y, kb.z, kb.w};
            #pragma unroll
            for (int i = 0; i < 4; i++)
                #pragma unroll
                for (int j = 0; j < 4; j++)
                    acc[i][j] += qv[i] * kv[j];
        }
        __syncthreads();   // all reads of qT complete before s overwrites it
        #pragma unroll
        for (int i = 0; i < 4; i++) {
            float4 sv = make_float4(acc[i][0] * scale, acc[i][1] * scale,
                                    acc[i][2] * scale, acc[i][3] * scale);
            *reinterpret_cast<float4*>(&s[(ty * 4 + i) * 64 + tx * 4]) = sv;
        }
    }
    __syncthreads();

    {
        const int warp = tid >> 5, lane = tid & 31;
        for (int r = warp; r < 64; r += 8) {
            float x0 = s[r * 64 + lane], x1 = s[r * 64 + 32 + lane];
            float mx = fmaxf(x0, x1);
            #pragma unroll
            for (int o = 16; o > 0; o >>= 1) mx = fmaxf(mx, __shfl_xor_sync(~0u, mx, o));
            float e0 = __expf(x0 - mx), e1 = __expf(x1 - mx);
            float sum = e0 + e1;
            #pragma unroll
            for (int o = 16; o > 0; o >>= 1) sum += __shfl_xor_sync(~0u, sum, o);
            float inv = 1.f / sum;
            s[r * 64 + lane] = e0 * inv;
            s[r * 64 + 32 + lane] = e1 * inv;
        }
    }
    __syncthreads();

    {
        const int tx = tid & 15, ty = tid >> 4;
        float acc[4][5] = {};
        for (int kk = 0; kk < 64; kk++) {
            float sa[4], vb[5];
            #pragma unroll
            for (int i = 0; i < 4; i++) sa[i] = s[(ty * 4 + i) * 64 + kk];
            #pragma unroll
            for (int j = 0; j < 5; j++) vb[j] = v[kk * SPV + tx * 5 + j];
            #pragma unroll
            for (int i = 0; i < 4; i++)
                #pragma unroll
                for (int j = 0; j < 5; j++)
                    acc[i][j] += sa[i] * vb[j];
        }
        __syncthreads();   // all reads of s complete before staging overwrites it
        #pragma unroll
        for (int i = 0; i < 4; i++) {
            int row = ty * 4 + i;
            #pragma unroll
            for (int j = 0; j < 5; j++) {
                float val = acc[i][j];
                __nv_bfloat16 hh = __float2bfloat16(val);
                stH[row * 80 + tx * 5 + j] = hh;
                stL[row * 80 + tx * 5 + j] = __float2bfloat16(val - __bfloat162float(hh));
            }
        }
    }
    __syncthreads();

    // coalesced writeout: 64 rows x 160B = 640 uint4 per buffer
    {
        const uint4* sh = reinterpret_cast<const uint4*>(stH);
        const uint4* sl = reinterpret_cast<const uint4*>(stL);
        for (int e = tid; e < 640; e += 256) {
            int row = e / 10, q = e % 10;
            long gb = ((long)(w * 64 + row) * HDIM + h * 80) / 8;  // uint4 units
            reinterpret_cast<uint4*>(outH)[gb + q] = sh[e];
            reinterpret_cast<uint4*>(outL)[gb + q] = sl[e];
        }
    }
}

// ---------------- fused (optional add) + RMSNorm, bf16 hi/lo out (vectorized) ----------------
__global__ void __launch_bounds__(256) rmsnorm_kernel(
    const float* __restrict__ a, const float* __restrict__ b,
    const float* __restrict__ w, float* __restrict__ sum_out,
    __nv_bfloat16* __restrict__ nh, __nv_bfloat16* __restrict__ nl)
{
    __shared__ float sv[HDIM];
    __shared__ float red[8];
    __shared__ float s_scale;
    const int row = blockIdx.x, tid = threadIdx.x;
    const long base = (long)row * HDIM;
    float ss = 0.f;
    for (int k = tid * 4; k < HDIM; k += 1024) {
        float4 va = *reinterpret_cast<const float4*>(a + base + k);
        if (b) {
            float4 vb = *reinterpret_cast<const float4*>(b + base + k);
            va.x += vb.x; va.y += vb.y; va.z += vb.z; va.w += vb.w;
        }
        *reinterpret_cast<float4*>(&sv[k]) = va;
        if (sum_out) *reinterpret_cast<float4*>(sum_out + base + k) = va;
        ss += va.x * va.x + va.y * va.y + va.z * va.z + va.w * va.w;
    }
    #pragma unroll
    for (int o = 16; o > 0; o >>= 1) ss += __shfl_xor_sync(~0u, ss, o);
    if ((tid & 31) == 0) red[tid >> 5] = ss;
    __syncthreads();
    if (tid == 0) {
        float t = 0.f;
        #pragma unroll
        for (int i = 0; i < 8; i++) t += red[i];
        s_scale = rsqrtf(t / (float)HDIM + 1e-6f);
    }
    __syncthreads();
    float sc = s_scale;
    for (int k = tid * 4; k < HDIM; k += 1024) {
        float4 va = *reinterpret_cast<const float4*>(&sv[k]);
        float4 vw = *reinterpret_cast<const float4*>(w + k);
        float vv[4] = {va.x * sc * vw.x, va.y * sc * vw.y,
                       va.z * sc * vw.z, va.w * sc * vw.w};
        __nv_bfloat16 th[4], tl[4];
        #pragma unroll
        for (int j = 0; j < 4; j++) {
            __nv_bfloat16 hh = __float2bfloat16(vv[j]);
            th[j] = hh;
            tl[j] = __float2bfloat16(vv[j] - __bfloat162float(hh));
        }
        *reinterpret_cast<uint2*>(nh + base + k) = *reinterpret_cast<uint2*>(th);
        *reinterpret_cast<uint2*>(nl + base + k) = *reinterpret_cast<uint2*>(tl);
    }
}

// ---------------- standalone GELU + bf16 hi/lo split (for split-K m0) ----------------
__global__ void __launch_bounds__(256) gelu_split_kernel(
    const float* __restrict__ in, __nv_bfloat16* __restrict__ oh,
    __nv_bfloat16* __restrict__ ol, long n4)
{
    for (long i = (long)blockIdx.x * 256 + threadIdx.x; i < n4; i += (long)gridDim.x * 256) {
        float4 v = *reinterpret_cast<const float4*>(in + 4 * i);
        float vv[4] = {v.x, v.y, v.z, v.w};
        __nv_bfloat16 th[4], tl[4];
        #pragma unroll
        for (int j = 0; j < 4; j++) {
            float x = vv[j];
            float g = 0.5f * x * (1.f + erff(x * 0.70710678118654752f));
            __nv_bfloat16 hh = __float2bfloat16(g);
            th[j] = hh;
            tl[j] = __float2bfloat16(g - __bfloat162float(hh));
        }
        *reinterpret_cast<uint2*>(oh + 4 * i) = *reinterpret_cast<uint2*>(th);
        *reinterpret_cast<uint2*>(ol + 4 * i) = *reinterpret_cast<uint2*>(tl);
    }
}

// ---------------- interleaved gate|up weight split ----------------
__global__ void __launch_bounds__(256) split_interleave_kernel(
    const float* __restrict__ gw, const float* __restrict__ uw,
    __nv_bfloat16* __restrict__ h, __nv_bfloat16* __restrict__ l, int rows)
{
    const int j4n = MH_P / 4;     // 856
    long total = (long)rows * j4n;
    for (long i = (long)blockIdx.x * 256 + threadIdx.x; i < total; i += (long)gridDim.x * 256) {
        int r = (int)(i / j4n);
        int j0 = (int)(i - (long)r * j4n) * 4;
        __nv_bfloat16 th[8], tl[8];
        #pragma unroll
        for (int jj = 0; jj < 4; ++jj) {
            int j = j0 + jj;
            float gv = (j < MHID) ? gw[(long)r * MHID + j] : 0.f;
            float uv = (j < MHID) ? uw[(long)r * MHID + j] : 0.f;
            __nv_bfloat16 gh = __float2bfloat16(gv);
            __nv_bfloat16 uh = __float2bfloat16(uv);
            th[2*jj]   = gh;
            th[2*jj+1] = uh;
            tl[2*jj]   = __float2bfloat16(gv - __bfloat162float(gh));
            tl[2*jj+1] = __float2bfloat16(uv - __bfloat162float(uh));
        }
        long o = (long)r * GU_N + 2 * j0;
        *reinterpret_cast<uint4*>(h + o) = *reinterpret_cast<uint4*>(th);
        *reinterpret_cast<uint4*>(l + o) = *reinterpret_cast<uint4*>(tl);
    }
}

// ---------------- interleaved gate|up bias fill ----------------
__global__ void __launch_bounds__(256) fill_bias_kernel(
    const float* __restrict__ gate_b, const float* __restrict__ up_b, float* __restrict__ out)
{
    int i = blockIdx.x * 256 + threadIdx.x;
    if (i >= NBLK * GU_N) return;
    int d = i / GU_N, c = i - d * GU_N;
    int j = c >> 1;
    float v = 0.f;
    if (j < MHID) v = (c & 1) ? up_b[d * MHID + j] : gate_b[d * MHID + j];
    out[i] = v;
}

// ---------------- fp32 -> bf16 hi/lo splits ----------------
__global__ void __launch_bounds__(256) split_kernel(
    const float4* __restrict__ in, __nv_bfloat16* __restrict__ h,
    __nv_bfloat16* __restrict__ l, long n4)
{
    for (long i = (long)blockIdx.x * 256 + threadIdx.x; i < n4; i += (long)gridDim.x * 256) {
        float4 v = in[i];
        __nv_bfloat16 th[4], tl[4];
        float vv[4] = {v.x, v.y, v.z, v.w};
        #pragma unroll
        for (int j = 0; j < 4; j++) {
            th[j] = __float2bfloat16(vv[j]);
            tl[j] = __float2bfloat16(vv[j] - __bfloat162float(th[j]));
        }
        *reinterpret_cast<uint2*>(h + 4 * i) = *reinterpret_cast<uint2*>(th);
        *reinterpret_cast<uint2*>(l + 4 * i) = *reinterpret_cast<uint2*>(tl);
    }
}

// ---------------- host ----------------
static inline dim3 ggrid(int M, int N, int S = 1) {
    return dim3((N + 127) / 128, (M + 127) / 128, S);
}

static inline void do_split(const float* src, __nv_bfloat16* h, __nv_bfloat16* l, long n) {
    long n4 = n / 4;
    int blocks = (int)((n4 + 255) / 256);
    if (blocks > 16384) blocks = 16384;
    split_kernel<<<blocks, 256>>>((const float4*)src, h, l, n4);
}

extern "C" void kernel_launch(void* const* d_in, const int* in_sizes, int n_in,
                              void* d_out, int out_size)
{
    const float* x       = (const float*)d_in[0];
    const float* cosb    = (const float*)d_in[1];
    const float* sinb    = (const float*)d_in[2];
    const float* patch_w = (const float*)d_in[3];
    const float* norm1_w = (const float*)d_in[4];
    const float* norm2_w = (const float*)d_in[5];
    const float* qkv_w   = (const float*)d_in[6];
    const float* qkv_b   = (const float*)d_in[7];
    const float* proj_w  = (const float*)d_in[8];
    const float* proj_b  = (const float*)d_in[9];
    const float* gate_w  = (const float*)d_in[10];
    const float* gate_b  = (const float*)d_in[11];
    const float* up_w    = (const float*)d_in[12];
    const float* up_b    = (const float*)d_in[13];
    const float* down_w  = (const float*)d_in[14];
    const float* down_b  = (const float*)d_in[15];
    const float* lnq_w   = (const float*)d_in[16];
    const float* m0_w    = (const float*)d_in[17];
    const float* m0_b    = (const float*)d_in[18];
    const float* m2_w    = (const float*)d_in[19];
    const float* m2_b    = (const float*)d_in[20];

    float* fs = nullptr;
    __nv_bfloat16* bs = nullptr;
    float* gub = nullptr;
    cudaGetSymbolAddress((void**)&fs, g_f32);
    cudaGetSymbolAddress((void**)&bs, g_bf16);
    cudaGetSymbolAddress((void**)&gub, g_bias);

    float* pX    = fs + F_X;
    float* pRES  = fs + F_RES;
    float* pHB   = fs + F_HB;
    float* pQKV  = fs + F_QKV;
    float* pM0   = fs + F_M0;

    __nv_bfloat16 *xH = bs+B_XH, *xL = bs+B_XL;
    __nv_bfloat16 *nH = bs+B_NH, *nL = bs+B_NL;
    __nv_bfloat16 *aH = bs+B_AH, *aL = bs+B_AL;
    __nv_bfloat16 *sH = bs+B_SH, *sL = bs+B_SL;
    __nv_bfloat16 *pwH = bs+B_PW,  *pwL = pwH + SZ_PW;
    __nv_bfloat16 *qwH = bs+B_QW,  *qwL = qwH + SZ_QW;
    __nv_bfloat16 *prH = bs+B_PRW, *prL = prH + SZ_PRW;
    __nv_bfloat16 *guH = bs+B_GUH, *guL = bs+B_GUL;
    __nv_bfloat16 *dwH = bs+B_DW,  *dwL = dwH + SZ_DW;
    __nv_bfloat16 *m0H = bs+B_M0W, *m0L = m0H + SZ_M0W;
    __nv_bfloat16 *m2H = bs+B_M2W, *m2L = m2H + SZ_M2W;

    cudaFuncSetAttribute(tcgemm_kernel<E_NONE>, cudaFuncAttributeMaxDynamicSharedMemorySize, GEMM_SMEM);
    cudaFuncSetAttribute(tcgemm_kernel<E_BIAS>, cudaFuncAttributeMaxDynamicSharedMemorySize, GEMM_SMEM);
    cudaFuncSetAttribute(tcgemm_kernel<E_BIAS_RES>, cudaFuncAttributeMaxDynamicSharedMemorySize, GEMM_SMEM);
    cudaFuncSetAttribute(tcgemm_kernel<E_SWIGLU>, cudaFuncAttributeMaxDynamicSharedMemorySize, GEMM_SMEM);
    cudaFuncSetAttribute(attn_kernel, cudaFuncAttributeMaxDynamicSharedMemorySize, ATTN_SMEM);

    do_split(x,       xH,  xL,  SZ_XS);
    do_split(patch_w, pwH, pwL, SZ_PW);
    do_split(qkv_w,   qwH, qwL, SZ_QW);
    do_split(proj_w,  prH, prL, SZ_PRW);
    split_interleave_kernel<<<16384, 256>>>(gate_w, up_w, guH, guL, NBLK * HDIM);

    // patch embed (split-K S=4, atomic)
    cudaMemsetAsync(pX, 0, SZ_LH * sizeof(float));
    tcgemm_kernel<E_NONE><<<ggrid(LTOK, HDIM, 4), GT, GEMM_SMEM>>>(
        xH, xL, pwH, pwL, nullptr, nullptr, pX, nullptr, nullptr,
        LTOK, HDIM, PDIM, PDIM, HDIM, HDIM);

    do_split(down_w,  dwH, dwL, SZ_DW);
    do_split(m0_w,    m0H, m0L, SZ_M0W);
    do_split(m2_w,    m2H, m2L, SZ_M2W);
    fill_bias_kernel<<<(NBLK * GU_N + 255) / 256, 256>>>(gate_b, up_b, gub);

    for (int d = 0; d < NBLK; d++) {
        rmsnorm_kernel<<<LTOK, 256>>>(pX, d == 0 ? nullptr : pRES,
                                      norm1_w + (long)d * HDIM, pHB, nH, nL);
        // qkv (S=1, plain store — big output, split-K hurts here)
        tcgemm_kernel<E_BIAS><<<ggrid(LTOK, 3 * HDIM), GT, GEMM_SMEM>>>(
            nH, nL, qwH + (long)d * HDIM * 3 * HDIM, qwL + (long)d * HDIM * 3 * HDIM,
            qkv_b + (long)d * 3 * HDIM, nullptr, pQKV, nullptr, nullptr,
            LTOK, 3 * HDIM, HDIM, HDIM, 3 * HDIM, 3 * HDIM);
        attn_kernel<<<NWIN * NHEAD, 256, ATTN_SMEM>>>(pQKV, cosb, sinb, aH, aL);
        // proj + residual (split-K S=4, atomic; bias+res added by z=0)
        cudaMemsetAsync(pRES, 0, SZ_LH * sizeof(float));
        tcgemm_kernel<E_BIAS_RES><<<ggrid(LTOK, HDIM, 4), GT, GEMM_SMEM>>>(
            aH, aL, prH + (long)d * HDIM * HDIM, prL + (long)d * HDIM * HDIM,
            proj_b + (long)d * HDIM, pHB, pRES, nullptr, nullptr,
            LTOK, HDIM, HDIM, HDIM, HDIM, HDIM);
        rmsnorm_kernel<<<LTOK, 256>>>(pRES, nullptr, norm2_w + (long)d * HDIM, nullptr, nH, nL);
        // merged interleaved gate|up GEMM with fused swiglu epilogue -> sH/sL
        tcgemm_kernel<E_SWIGLU><<<ggrid(LTOK, GU_N), GT, GEMM_SMEM>>>(
            nH, nL, guH + (long)d * HDIM * GU_N, guL + (long)d * HDIM * GU_N,
            gub + (long)d * GU_N, nullptr, nullptr, sH, sL,
            LTOK, GU_N, HDIM, HDIM, GU_N, GU_N);
        // down (split-K S=4, atomic)
        cudaMemsetAsync(pX, 0, SZ_LH * sizeof(float));
        tcgemm_kernel<E_BIAS><<<ggrid(LTOK, HDIM, 4), GT, GEMM_SMEM>>>(
            sH, sL, dwH + (long)d * MHID * HDIM, dwL + (long)d * MHID * HDIM,
            down_b + (long)d * HDIM, nullptr, pX, nullptr, nullptr,
            LTOK, HDIM, MHID, MH_P, HDIM, HDIM);
    }

    // merger
    rmsnorm_kernel<<<LTOK, 256>>>(pX, pRES, lnq_w, nullptr, nH, nL);
    // m0 (split-K S=4 into pM0, then standalone gelu+split)
    cudaMemsetAsync(pM0, 0, (long)LMERG * H4 * sizeof(float));
    tcgemm_kernel<E_BIAS><<<ggrid(LMERG, H4, 4), GT, GEMM_SMEM>>>(
        nH, nL, m0H, m0L, m0_b, nullptr, pM0, nullptr, nullptr,
        LMERG, H4, H4, H4, H4, H4);
    gelu_split_kernel<<<16384, 256>>>(pM0, aH, aL, (long)LMERG * H4 / 4);
    // m2 (split-K S=4 into d_out)
    cudaMemsetAsync(d_out, 0, (long)out_size * sizeof(float));
    tcgemm_kernel<E_BIAS><<<ggrid(LMERG, DMODEL, 4), GT, GEMM_SMEM>>>(
        aH, aL, m2H, m2L, m2_b, nullptr, (float*)d_out, nullptr, nullptr,
        LMERG, DMODEL, H4, H4, DMODEL, DMODEL);
}

// round 17
// speedup vs baseline: 1.3727x; 1.3351x over previous
#include <cuda_runtime.h>
#include <cuda_bf16.h>
#include <math.h>
#include <stdint.h>

// ---------------- problem constants ----------------
#define LTOK 8192
#define HDIM 1280
#define MHID 3420
#define MH_P 3424
#define GU_N 6848
#define NBLK 4
#define NWIN 128
#define PDIM 1176
#define DMODEL 3584
#define H4 5120
#define LMERG 2048

// ---------------- fp32 accumulator scratch ----------------
static constexpr long SZ_LH  = (long)LTOK * HDIM;
static constexpr long SZ_L3H = (long)LTOK * 3 * HDIM;
static constexpr long F_X    = 0;
static constexpr long F_RES  = F_X   + SZ_LH;
static constexpr long F_HB   = F_RES + SZ_LH;
static constexpr long F_QKV  = F_HB  + SZ_LH;
static constexpr long F_M0   = F_QKV + SZ_L3H;
static constexpr long F_TOTAL = F_M0 + (long)LMERG * H4;
__device__ float g_f32[F_TOTAL];

__device__ float g_bias[NBLK * GU_N];

// ---------------- tf32 operand scratch (fp32 storage, tf32-rounded) ----------------
static constexpr long T_X   = 0;                               // [LTOK][PDIM]
static constexpr long T_N   = T_X   + (long)LTOK * PDIM;       // [LTOK][HDIM] / merger [2048][5120]
static constexpr long T_A   = T_N   + (long)LTOK * HDIM;       // [LTOK][HDIM] / merger [2048][5120]
static constexpr long T_S   = T_A   + (long)LTOK * HDIM;       // [LTOK][MH_P]
static constexpr long T_PW  = T_S   + (long)LTOK * MH_P;
static constexpr long T_QW  = T_PW  + (long)PDIM * HDIM;
static constexpr long T_PRW = T_QW  + 4L * HDIM * 3 * HDIM;
static constexpr long T_GU  = T_PRW + 4L * HDIM * HDIM;
static constexpr long T_DW  = T_GU  + 4L * HDIM * GU_N;        // 4x[MH_P][HDIM], zero-padded rows
static constexpr long T_M0  = T_DW  + 4L * MH_P * HDIM;
static constexpr long T_M2  = T_M0  + (long)H4 * H4;
static constexpr long T_TOTAL = T_M2 + (long)H4 * DMODEL;
__device__ float g_tf[T_TOTAL];

// ---------------- PTX helpers (base sm_103 target only!) ----------------
__device__ __forceinline__ uint32_t smem_to_u32(const void* p) {
    uint32_t a;
    asm("{ .reg .u64 t; cvta.to.shared.u64 t, %1; cvt.u32.u64 %0, t; }" : "=r"(a) : "l"(p));
    return a;
}
__device__ __forceinline__ void cp16(uint32_t dst, const void* src, int bytes) {
    asm volatile("cp.async.cg.shared.global [%0], [%1], 16, %2;"
                 :: "r"(dst), "l"(src), "r"(bytes));
}
#define CP_COMMIT() asm volatile("cp.async.commit_group;" ::: "memory")
#define CP_WAIT2()  asm volatile("cp.async.wait_group 2;" ::: "memory")

__device__ __forceinline__ float tf32r(float x) {
    uint32_t u;
    asm("cvt.rna.tf32.f32 %0, %1;" : "=r"(u) : "f"(x));
    return __uint_as_float(u);
}
__device__ __forceinline__ void mma_tf32(float c[4], uint32_t a0, uint32_t a1,
                                         uint32_t a2, uint32_t a3,
                                         uint32_t b0, uint32_t b1) {
    asm volatile(
        "mma.sync.aligned.m16n8k8.row.col.f32.tf32.tf32.f32 "
        "{%0,%1,%2,%3}, {%4,%5,%6,%7}, {%8,%9}, {%0,%1,%2,%3};"
        : "+f"(c[0]), "+f"(c[1]), "+f"(c[2]), "+f"(c[3])
        : "r"(a0), "r"(a1), "r"(a2), "r"(a3), "r"(b0), "r"(b1));
}

// ---------------- tf32 tensor-core GEMM (single pass, fp32 accum, optional split-K) ----------------
enum { E_NONE = 0, E_BIAS = 1, E_BIAS_RES = 2, E_SWIGLU = 3 };

#define AT_STRIDE 36                        // fp32 words per A row (32 + pad4)
#define BT_STRIDE 136                       // fp32 words per B row (128 + pad8)
#define A_TILE_B (128 * AT_STRIDE * 4)      // 18432
#define B_TILE_B (32 * BT_STRIDE * 4)       // 17408
#define STAGE_B  (A_TILE_B + B_TILE_B)      // 35840
#define GEMM_SMEM (3 * STAGE_B)             // 107520
#define GT 256

template<int EPI>
__global__ void __launch_bounds__(GT, 2) tcgemm_kernel(
    const float* __restrict__ A, const float* __restrict__ B,
    const float* __restrict__ bias, const float* __restrict__ res,
    float* __restrict__ C, float* __restrict__ Osw,
    int M, int N, int K, int lda, int ldb, int ldc)
{
    extern __shared__ __align__(16) char sm[];
    const uint32_t smem_u = smem_to_u32(sm);
    const int tid = threadIdx.x;
    const int lane = tid & 31, wid = tid >> 5;
    const int wm = wid >> 2, wn = wid & 3;        // 2(M) x 4(N) warp grid, warp tile 64x32
    const int row0 = blockIdx.y * 128, col0 = blockIdx.x * 128;

    const int nc_tot = (K + 31) / 32;
    const int S = gridDim.z;
    const int per = (nc_tot + S - 1) / S;
    const int c0 = blockIdx.z * per;
    int c1 = c0 + per; if (c1 > nc_tot) c1 = nc_tot;
    const int myn = (c1 > c0) ? (c1 - c0) : 0;

    auto load_stage = [&](int st, int c) {
        const uint32_t sbase = smem_u + st * STAGE_B;
        const int k0 = c * 32;
        // A: 128 rows x 32 fp32 (8 x 16B per row) = 1024 vecs
        #pragma unroll
        for (int it = 0; it < 4; ++it) {
            int e = tid + it * 256;
            int r = e >> 3, q = e & 7;
            int gr = row0 + r;
            int gk = k0 + q * 4;
            int bytes = (K - gk) * 4;
            bytes = bytes < 0 ? 0 : (bytes > 16 ? 16 : bytes);
            const float* g = A + (long)gr * lda + (bytes > 0 ? gk : 0);
            cp16(sbase + r * (AT_STRIDE * 4) + q * 16, g, bytes);
        }
        // B: 32 rows x 128 fp32 (32 x 16B per row) = 1024 vecs
        #pragma unroll
        for (int it = 0; it < 4; ++it) {
            int e = tid + it * 256;
            int r = e >> 5, q = e & 31;
            int gk = k0 + r;
            int gc = col0 + q * 4;
            int bytes = (N - gc) * 4;
            bytes = bytes < 0 ? 0 : (bytes > 16 ? 16 : bytes);
            if (gk >= K) bytes = 0;
            const float* g = B + (long)(gk < K ? gk : 0) * ldb + (bytes > 0 ? gc : 0);
            cp16(sbase + A_TILE_B + r * (BT_STRIDE * 4) + q * 16, g, bytes);
        }
    };

    const int g = lane >> 2, c4 = lane & 3;

    float acc[4][4][4];
    #pragma unroll
    for (int i = 0; i < 4; ++i)
        #pragma unroll
        for (int j = 0; j < 4; ++j)
            #pragma unroll
            for (int r = 0; r < 4; ++r) acc[i][j][r] = 0.f;

    #pragma unroll
    for (int s = 0; s < 3; ++s) {
        if (s < myn) load_stage(s, c0 + s);
        CP_COMMIT();
    }

    for (int cc = 0; cc < myn; ++cc) {
        CP_WAIT2();
        __syncthreads();
        const int st = cc % 3;
        const float* As = reinterpret_cast<const float*>(sm + st * STAGE_B);
        const float* Bs = reinterpret_cast<const float*>(sm + st * STAGE_B + A_TILE_B);

        #pragma unroll
        for (int ks = 0; ks < 4; ++ks) {
            const int kb = ks * 8;
            uint32_t a0[4], a1[4], a2[4], a3[4];
            #pragma unroll
            for (int i = 0; i < 4; ++i) {
                int r0 = (wm * 64 + i * 16 + g) * AT_STRIDE + kb + c4;
                a0[i] = __float_as_uint(As[r0]);
                a1[i] = __float_as_uint(As[r0 + 8 * AT_STRIDE]);
                a2[i] = __float_as_uint(As[r0 + 4]);
                a3[i] = __float_as_uint(As[r0 + 8 * AT_STRIDE + 4]);
            }
            #pragma unroll
            for (int nt = 0; nt < 4; ++nt) {
                int nb = wn * 32 + nt * 8 + g;
                uint32_t b0 = __float_as_uint(Bs[(kb + c4) * BT_STRIDE + nb]);
                uint32_t b1 = __float_as_uint(Bs[(kb + c4 + 4) * BT_STRIDE + nb]);
                #pragma unroll
                for (int i = 0; i < 4; ++i)
                    mma_tf32(acc[i][nt], a0[i], a1[i], a2[i], a3[i], b0, b1);
            }
        }
        __syncthreads();
        if (cc + 3 < myn) load_stage(st, c0 + cc + 3);
        CP_COMMIT();
    }

    const bool add_const = (blockIdx.z == 0);
    const int t = lane & 3;
    #pragma unroll
    for (int i = 0; i < 4; ++i) {
        #pragma unroll
        for (int j = 0; j < 4; ++j) {
            int col = col0 + wn * 32 + j * 8 + t * 2;
            if (col >= N) continue;
            float b0 = 0.f, b1 = 0.f;
            if (EPI != E_NONE && add_const) { b0 = bias[col]; b1 = bias[col + 1]; }
            #pragma unroll
            for (int rr = 0; rr < 2; ++rr) {
                int row = row0 + wm * 64 + i * 16 + g + rr * 8;
                if (row >= M) continue;
                float v0 = acc[i][j][rr * 2 + 0] + b0;
                float v1 = acc[i][j][rr * 2 + 1] + b1;
                if (EPI == E_SWIGLU) {
                    float sw = v0 / (1.f + __expf(-v0)) * v1;
                    Osw[(long)row * MH_P + (col >> 1)] = tf32r(sw);
                    continue;
                }
                long idx = (long)row * ldc + col;
                if (EPI == E_BIAS_RES && add_const) { v0 += res[idx]; v1 += res[idx + 1]; }
                if (gridDim.z == 1) {
                    *reinterpret_cast<float2*>(C + idx) = make_float2(v0, v1);
                } else {
                    atomicAdd(C + idx, v0);
                    atomicAdd(C + idx + 1, v1);
                }
            }
        }
    }
}

// ---------------- fused windowed attention with inline RoPE (fp32, tf32 out) ----------------
#define SPT 68
#define SPV 81
#define ATTN_SMEM ((2 * 80 * SPT + 64 * SPV) * 4)

__global__ void __launch_bounds__(256) attn_kernel(
    const float* __restrict__ qkv, const float* __restrict__ cosb,
    const float* __restrict__ sinb, float* __restrict__ outT)
{
    extern __shared__ float smf[];
    float* qT = smf;
    float* kT = smf + 80 * SPT;
    float* v  = smf + 2 * 80 * SPT;
    float* s  = smf;                  // aliases qT
    float* stF = smf;                 // output staging aliases s (after PV)

    const int w = blockIdx.x >> 4;
    const int h = blockIdx.x & 15;
    const int tid = threadIdx.x;
    const float scale = 0.11180339887498949f;

    for (int e = tid; e < 64 * 80; e += 256) {
        int t = e / 80, j = e % 80;
        int l = w * 64 + t;
        long base = (long)l * (3 * HDIM) + h * 80;
        float c = cosb[l * 80 + j], sn = sinb[l * 80 + j];
        float qv = qkv[base + j];
        float qr = (j < 40) ? -qkv[base + j + 40] : qkv[base + j - 40];
        qT[j * SPT + t] = qv * c + qr * sn;
        float kv = qkv[base + HDIM + j];
        float kr = (j < 40) ? -qkv[base + HDIM + j + 40] : qkv[base + HDIM + j - 40];
        kT[j * SPT + t] = kv * c + kr * sn;
        v[t * SPV + j] = qkv[base + 2 * HDIM + j];
    }
    __syncthreads();

    {
        const int tx = tid & 15, ty = tid >> 4;
        float acc[4][4] = {};
        for (int d = 0; d < 80; d++) {
            float4 qa = *reinterpret_cast<const float4*>(&qT[d * SPT + ty * 4]);
            float4 kb = *reinterpret_cast<const float4*>(&kT[d * SPT + tx * 4]);
            float qv[4] = {qa.x, qa.y, qa.z, qa.w};
            float kv[4] = {kb.x, kb.y, kb.z, kb.w};
            #pragma unroll
            for (int i = 0; i < 4; i++)
                #pragma unroll
                for (int j = 0; j < 4; j++)
                    acc[i][j] += qv[i] * kv[j];
        }
        __syncthreads();
        #pragma unroll
        for (int i = 0; i < 4; i++) {
            float4 sv = make_float4(acc[i][0] * scale, acc[i][1] * scale,
                                    acc[i][2] * scale, acc[i][3] * scale);
            *reinterpret_cast<float4*>(&s[(ty * 4 + i) * 64 + tx * 4]) = sv;
        }
    }
    __syncthreads();

    {
        const int warp = tid >> 5, lane = tid & 31;
        for (int r = warp; r < 64; r += 8) {
            float x0 = s[r * 64 + lane], x1 = s[r * 64 + 32 + lane];
            float mx = fmaxf(x0, x1);
            #pragma unroll
            for (int o = 16; o > 0; o >>= 1) mx = fmaxf(mx, __shfl_xor_sync(~0u, mx, o));
            float e0 = __expf(x0 - mx), e1 = __expf(x1 - mx);
            float sum = e0 + e1;
            #pragma unroll
            for (int o = 16; o > 0; o >>= 1) sum += __shfl_xor_sync(~0u, sum, o);
            float inv = 1.f / sum;
            s[r * 64 + lane] = e0 * inv;
            s[r * 64 + 32 + lane] = e1 * inv;
        }
    }
    __syncthreads();

    {
        const int tx = tid & 15, ty = tid >> 4;
        float acc[4][5] = {};
        for (int kk = 0; kk < 64; kk++) {
            float sa[4], vb[5];
            #pragma unroll
            for (int i = 0; i < 4; i++) sa[i] = s[(ty * 4 + i) * 64 + kk];
            #pragma unroll
            for (int j = 0; j < 5; j++) vb[j] = v[kk * SPV + tx * 5 + j];
            #pragma unroll
            for (int i = 0; i < 4; i++)
                #pragma unroll
                for (int j = 0; j < 5; j++)
                    acc[i][j] += sa[i] * vb[j];
        }
        __syncthreads();
        #pragma unroll
        for (int i = 0; i < 4; i++) {
            int row = ty * 4 + i;
            #pragma unroll
            for (int j = 0; j < 5; j++)
                stF[row * 80 + tx * 5 + j] = tf32r(acc[i][j]);
        }
    }
    __syncthreads();

    // coalesced writeout: 64 rows x 320B = 1280 float4
    {
        const float4* sf = reinterpret_cast<const float4*>(stF);
        for (int e = tid; e < 1280; e += 256) {
            int row = e / 20, q = e % 20;
            long gb = (long)(w * 64 + row) * (HDIM / 4) + h * 20 + q;
            reinterpret_cast<float4*>(outT)[gb] = sf[e];
        }
    }
}

// ---------------- fused (optional add) + RMSNorm, tf32 fp32 out ----------------
__global__ void __launch_bounds__(256) rmsnorm_kernel(
    const float* __restrict__ a, const float* __restrict__ b,
    const float* __restrict__ w, float* __restrict__ sum_out,
    float* __restrict__ nt)
{
    __shared__ float sv[HDIM];
    __shared__ float red[8];
    __shared__ float s_scale;
    const int row = blockIdx.x, tid = threadIdx.x;
    const long base = (long)row * HDIM;
    float ss = 0.f;
    for (int k = tid * 4; k < HDIM; k += 1024) {
        float4 va = *reinterpret_cast<const float4*>(a + base + k);
        if (b) {
            float4 vb = *reinterpret_cast<const float4*>(b + base + k);
            va.x += vb.x; va.y += vb.y; va.z += vb.z; va.w += vb.w;
        }
        *reinterpret_cast<float4*>(&sv[k]) = va;
        if (sum_out) *reinterpret_cast<float4*>(sum_out + base + k) = va;
        ss += va.x * va.x + va.y * va.y + va.z * va.z + va.w * va.w;
    }
    #pragma unroll
    for (int o = 16; o > 0; o >>= 1) ss += __shfl_xor_sync(~0u, ss, o);
    if ((tid & 31) == 0) red[tid >> 5] = ss;
    __syncthreads();
    if (tid == 0) {
        float t = 0.f;
        #pragma unroll
        for (int i = 0; i < 8; i++) t += red[i];
        s_scale = rsqrtf(t / (float)HDIM + 1e-6f);
    }
    __syncthreads();
    float sc = s_scale;
    for (int k = tid * 4; k < HDIM; k += 1024) {
        float4 va = *reinterpret_cast<const float4*>(&sv[k]);
        float4 vw = *reinterpret_cast<const float4*>(w + k);
        float4 o = make_float4(tf32r(va.x * sc * vw.x), tf32r(va.y * sc * vw.y),
                               tf32r(va.z * sc * vw.z), tf32r(va.w * sc * vw.w));
        *reinterpret_cast<float4*>(nt + base + k) = o;
    }
}

// ---------------- GELU + tf32 cvt (for split-K m0) ----------------
__global__ void __launch_bounds__(256) gelu_cvt_kernel(
    const float* __restrict__ in, float* __restrict__ out, long n4)
{
    for (long i = (long)blockIdx.x * 256 + threadIdx.x; i < n4; i += (long)gridDim.x * 256) {
        float4 vv = *reinterpret_cast<const float4*>(in + 4 * i);
        float r[4] = {vv.x, vv.y, vv.z, vv.w};
        #pragma unroll
        for (int j = 0; j < 4; j++) {
            float x = r[j];
            r[j] = tf32r(0.5f * x * (1.f + erff(x * 0.70710678118654752f)));
        }
        *reinterpret_cast<float4*>(out + 4 * i) = make_float4(r[0], r[1], r[2], r[3]);
    }
}

// ---------------- weight fp32 -> tf32 with optional row padding ----------------
__global__ void __launch_bounds__(256) cvt_pad_kernel(
    const float* __restrict__ in, float* __restrict__ out, int K, int KP, int N)
{
    int n4 = N >> 2;
    long total = (long)KP * n4;
    for (long i = (long)blockIdx.x * 256 + threadIdx.x; i < total; i += (long)gridDim.x * 256) {
        int r = (int)(i / n4);
        int c4 = (int)(i - (long)r * n4) * 4;
        float4 o = make_float4(0.f, 0.f, 0.f, 0.f);
        if (r < K) {
            float4 vv = *reinterpret_cast<const float4*>(in + (long)r * N + c4);
            o = make_float4(tf32r(vv.x), tf32r(vv.y), tf32r(vv.z), tf32r(vv.w));
        }
        *reinterpret_cast<float4*>(out + (long)r * N + c4) = o;
    }
}

// ---------------- interleaved gate|up weight cvt: out[r][2j]=gate, [r][2j+1]=up ----------------
__global__ void __launch_bounds__(256) interleave_cvt_kernel(
    const float* __restrict__ gw, const float* __restrict__ uw,
    float* __restrict__ out, int rows)
{
    const int j2n = MH_P / 2;    // 1712 pairs of j per row
    long total = (long)rows * j2n;
    for (long i = (long)blockIdx.x * 256 + threadIdx.x; i < total; i += (long)gridDim.x * 256) {
        int r = (int)(i / j2n);
        int j0 = (int)(i - (long)r * j2n) * 2;
        float4 o;
        float g0 = (j0 < MHID) ? gw[(long)r * MHID + j0] : 0.f;
        float u0 = (j0 < MHID) ? uw[(long)r * MHID + j0] : 0.f;
        float g1 = (j0 + 1 < MHID) ? gw[(long)r * MHID + j0 + 1] : 0.f;
        float u1 = (j0 + 1 < MHID) ? uw[(long)r * MHID + j0 + 1] : 0.f;
        o.x = tf32r(g0); o.y = tf32r(u0); o.z = tf32r(g1); o.w = tf32r(u1);
        *reinterpret_cast<float4*>(out + (long)r * GU_N + 2 * j0) = o;
    }
}

// ---------------- interleaved gate|up bias fill ----------------
__global__ void __launch_bounds__(256) fill_bias_kernel(
    const float* __restrict__ gate_b, const float* __restrict__ up_b, float* __restrict__ out)
{
    int i = blockIdx.x * 256 + threadIdx.x;
    if (i >= NBLK * GU_N) return;
    int d = i / GU_N, c = i - d * GU_N;
    int j = c >> 1;
    float v = 0.f;
    if (j < MHID) v = (c & 1) ? up_b[d * MHID + j] : gate_b[d * MHID + j];
    out[i] = v;
}

// ---------------- host ----------------
static inline dim3 ggrid(int M, int N, int S = 1) {
    return dim3((N + 127) / 128, (M + 127) / 128, S);
}
static inline void do_cvt(const float* src, float* dst, int K, int KP, int N) {
    long total = (long)KP * (N / 4);
    int blocks = (int)((total + 255) / 256);
    if (blocks > 16384) blocks = 16384;
    cvt_pad_kernel<<<blocks, 256>>>(src, dst, K, KP, N);
}

extern "C" void kernel_launch(void* const* d_in, const int* in_sizes, int n_in,
                              void* d_out, int out_size)
{
    const float* x       = (const float*)d_in[0];
    const float* cosb    = (const float*)d_in[1];
    const float* sinb    = (const float*)d_in[2];
    const float* patch_w = (const float*)d_in[3];
    const float* norm1_w = (const float*)d_in[4];
    const float* norm2_w = (const float*)d_in[5];
    const float* qkv_w   = (const float*)d_in[6];
    const float* qkv_b   = (const float*)d_in[7];
    const float* proj_w  = (const float*)d_in[8];
    const float* proj_b  = (const float*)d_in[9];
    const float* gate_w  = (const float*)d_in[10];
    const float* gate_b  = (const float*)d_in[11];
    const float* up_w    = (const float*)d_in[12];
    const float* up_b    = (const float*)d_in[13];
    const float* down_w  = (const float*)d_in[14];
    const float* down_b  = (const float*)d_in[15];
    const float* lnq_w   = (const float*)d_in[16];
    const float* m0_w    = (const float*)d_in[17];
    const float* m0_b    = (const float*)d_in[18];
    const float* m2_w    = (const float*)d_in[19];
    const float* m2_b    = (const float*)d_in[20];

    float* fs = nullptr; float* tf = nullptr; float* gub = nullptr;
    cudaGetSymbolAddress((void**)&fs, g_f32);
    cudaGetSymbolAddress((void**)&tf, g_tf);
    cudaGetSymbolAddress((void**)&gub, g_bias);

    float* pX    = fs + F_X;
    float* pRES  = fs + F_RES;
    float* pHB   = fs + F_HB;
    float* pQKV  = fs + F_QKV;
    float* pM0   = fs + F_M0;

    float *xT = tf+T_X, *nT = tf+T_N, *aT = tf+T_A, *sT = tf+T_S;
    float *pwT = tf+T_PW, *qwT = tf+T_QW, *prT = tf+T_PRW, *guT = tf+T_GU;
    float *dwT = tf+T_DW, *m0T = tf+T_M0, *m2T = tf+T_M2;

    cudaFuncSetAttribute(tcgemm_kernel<E_NONE>, cudaFuncAttributeMaxDynamicSharedMemorySize, GEMM_SMEM);
    cudaFuncSetAttribute(tcgemm_kernel<E_BIAS>, cudaFuncAttributeMaxDynamicSharedMemorySize, GEMM_SMEM);
    cudaFuncSetAttribute(tcgemm_kernel<E_BIAS_RES>, cudaFuncAttributeMaxDynamicSharedMemorySize, GEMM_SMEM);
    cudaFuncSetAttribute(tcgemm_kernel<E_SWIGLU>, cudaFuncAttributeMaxDynamicSharedMemorySize, GEMM_SMEM);
    cudaFuncSetAttribute(attn_kernel, cudaFuncAttributeMaxDynamicSharedMemorySize, ATTN_SMEM);

    // weight / input conversion to tf32
    do_cvt(x, xT, LTOK, LTOK, PDIM);
    do_cvt(patch_w, pwT, PDIM, PDIM, HDIM);
    do_cvt(qkv_w, qwT, NBLK * HDIM, NBLK * HDIM, 3 * HDIM);
    do_cvt(proj_w, prT, NBLK * HDIM, NBLK * HDIM, HDIM);
    {
        long total = (long)(NBLK * HDIM) * (MH_P / 2);
        int blocks = (int)((total + 255) / 256);
        if (blocks > 16384) blocks = 16384;
        interleave_cvt_kernel<<<blocks, 256>>>(gate_w, up_w, guT, NBLK * HDIM);
    }
    for (int d = 0; d < NBLK; d++)
        do_cvt(down_w + (long)d * MHID * HDIM, dwT + (long)d * MH_P * HDIM, MHID, MH_P, HDIM);
    do_cvt(m0_w, m0T, H4, H4, H4);
    do_cvt(m2_w, m2T, H4, H4, DMODEL);
    fill_bias_kernel<<<(NBLK * GU_N + 255) / 256, 256>>>(gate_b, up_b, gub);

    // patch embed (split-K S=4, atomic)
    cudaMemsetAsync(pX, 0, SZ_LH * sizeof(float));
    tcgemm_kernel<E_NONE><<<ggrid(LTOK, HDIM, 4), GT, GEMM_SMEM>>>(
        xT, pwT, nullptr, nullptr, pX, nullptr,
        LTOK, HDIM, PDIM, PDIM, HDIM, HDIM);

    for (int d = 0; d < NBLK; d++) {
        rmsnorm_kernel<<<LTOK, 256>>>(pX, d == 0 ? nullptr : pRES,
                                      norm1_w + (long)d * HDIM, pHB, nT);
        // qkv (S=1)
        tcgemm_kernel<E_BIAS><<<ggrid(LTOK, 3 * HDIM), GT, GEMM_SMEM>>>(
            nT, qwT + (long)d * HDIM * 3 * HDIM, qkv_b + (long)d * 3 * HDIM,
            nullptr, pQKV, nullptr,
            LTOK, 3 * HDIM, HDIM, HDIM, 3 * HDIM, 3 * HDIM);
        attn_kernel<<<NWIN * 16, 256, ATTN_SMEM>>>(pQKV, cosb, sinb, aT);
        // proj + residual (split-K S=4)
        cudaMemsetAsync(pRES, 0, SZ_LH * sizeof(float));
        tcgemm_kernel<E_BIAS_RES><<<ggrid(LTOK, HDIM, 4), GT, GEMM_SMEM>>>(
            aT, prT + (long)d * HDIM * HDIM, proj_b + (long)d * HDIM,
            pHB, pRES, nullptr,
            LTOK, HDIM, HDIM, HDIM, HDIM, HDIM);
        rmsnorm_kernel<<<LTOK, 256>>>(pRES, nullptr, norm2_w + (long)d * HDIM, nullptr, nT);
        // merged interleaved gate|up GEMM with fused swiglu epilogue -> sT
        tcgemm_kernel<E_SWIGLU><<<ggrid(LTOK, GU_N), GT, GEMM_SMEM>>>(
            nT, guT + (long)d * HDIM * GU_N, gub + (long)d * GU_N,
            nullptr, nullptr, sT,
            LTOK, GU_N, HDIM, HDIM, GU_N, GU_N);
        // down (split-K S=4; K padded to MH_P with zeroed operands)
        cudaMemsetAsync(pX, 0, SZ_LH * sizeof(float));
        tcgemm_kernel<E_BIAS><<<ggrid(LTOK, HDIM, 4), GT, GEMM_SMEM>>>(
            sT, dwT + (long)d * MH_P * HDIM, down_b + (long)d * HDIM,
            nullptr, pX, nullptr,
            LTOK, HDIM, MH_P, MH_P, HDIM, HDIM);
    }

    // merger
    rmsnorm_kernel<<<LTOK, 256>>>(pX, pRES, lnq_w, nullptr, nT);
    // m0 (split-K S=4 into pM0, then gelu + tf32 cvt into aT)
    cudaMemsetAsync(pM0, 0, (long)LMERG * H4 * sizeof(float));
    tcgemm_kernel<E_BIAS><<<ggrid(LMERG, H4, 4), GT, GEMM_SMEM>>>(
        nT, m0T, m0_b, nullptr, pM0, nullptr,
        LMERG, H4, H4, H4, H4, H4);
    gelu_cvt_kernel<<<16384, 256>>>(pM0, aT, (long)LMERG * H4 / 4);
    // m2 (split-K S=4 into d_out)
    cudaMemsetAsync(d_out, 0, (long)out_size * sizeof(float));
    tcgemm_kernel<E_BIAS><<<ggrid(LMERG, DMODEL, 4), GT, GEMM_SMEM>>>(
        aT, m2T, m2_b, nullptr, (float*)d_out, nullptr,
        LMERG, DMODEL, H4, H4, DMODEL, DMODEL);
}